// round 1
// baseline (speedup 1.0000x reference)
#include <cuda_runtime.h>
#include <cuda_bf16.h>

// ---------------- problem dims ----------------
#define LSEQ 2048
#define DMODEL 512
#define DPROJ 2568
#define GN 4          // groups
#define NS 32         // d_state
#define RRK 2         // rank R
#define HH 16         // heads
#define PP 64         // head dim
#define NC 16         // chunks
#define CH 128        // chunk len
#define EPSV 1e-5f

// proj row offsets: z[0,1024) x[1024,2048) B[2048,2304) C[2304,2560) dt[2560,2564) lam[2564,2568)

// ---------------- scratch (device globals; no allocs allowed) ----------------
__device__ float  g_proj [LSEQ*DPROJ];        // 21 MB
__device__ float  g_zsilu[LSEQ*1024];
__device__ float  g_xsilu[LSEQ*1024];
__device__ float  g_Bm   [LSEQ*GN*64];        // [L][G][n*R+r]
__device__ float  g_Cm   [LSEQ*GN*64];
__device__ float4 g_scal [LSEQ*GN];           // (dt, lam, decay, 0)
__device__ float  g_sdt  [LSEQ*GN];           // cumsum of dt
__device__ float  g_Dc   [NC*GN];             // per-chunk decay product
__device__ float  g_xup  [LSEQ*HH*128];       // [L*H][p*R+r]
__device__ float  g_F    [NC*HH*PP*NS];       // chunk-local final states [c][h][p][n]
__device__ float  g_S    [NC*HH*PP*NS];       // state entering chunk     [c][h][p][n]
__device__ float  g_yraw [LSEQ*HH*128];       // [L*H][p*R+r]
__device__ float  g_y3   [LSEQ*1024];         // gated inner output

// ---------------- generic tiled SGEMM: C = A[MxK] @ B[KxN] (+bias) ----------------
template<int BM,int BN,int BK,int TM,int TN>
__global__ void k_sgemm(int M, int N, int K,
                        const float* __restrict__ A,
                        const float* __restrict__ B,
                        const float* __restrict__ bias,
                        float* __restrict__ C)
{
    __shared__ float As[BK][BM+4];
    __shared__ float Bs[BK][BN];
    const int NT  = (BM/TM)*(BN/TN);
    const int tid = threadIdx.x;
    const int TX  = BN/TN;
    const int tcol = tid % TX;
    const int trow = tid / TX;
    const int rowBase = blockIdx.y * BM;
    const int colBase = blockIdx.x * BN;

    float acc[TM][TN];
#pragma unroll
    for (int i=0;i<TM;i++)
#pragma unroll
        for (int j=0;j<TN;j++) acc[i][j]=0.f;

    for (int k0=0;k0<K;k0+=BK){
        for (int i=tid;i<BM*BK;i+=NT){
            int r = i / BK, c = i % BK;
            int gr = rowBase + r;
            As[c][r] = (gr < M) ? A[(size_t)gr*K + (k0+c)] : 0.f;
        }
        for (int i=tid;i<BK*BN;i+=NT){
            int r = i / BN, c = i % BN;
            int gc = colBase + c;
            Bs[r][c] = (gc < N) ? B[(size_t)(k0+r)*N + gc] : 0.f;
        }
        __syncthreads();
#pragma unroll
        for (int kk=0;kk<BK;kk++){
            float ra[TM], rb[TN];
#pragma unroll
            for (int i=0;i<TM;i++) ra[i] = As[kk][trow*TM+i];
#pragma unroll
            for (int j=0;j<TN;j++) rb[j] = Bs[kk][tcol*TN+j];
#pragma unroll
            for (int i=0;i<TM;i++)
#pragma unroll
                for (int j=0;j<TN;j++) acc[i][j] += ra[i]*rb[j];
        }
        __syncthreads();
    }
#pragma unroll
    for (int i=0;i<TM;i++){
        int gr = rowBase + trow*TM + i;
        if (gr >= M) continue;
#pragma unroll
        for (int j=0;j<TN;j++){
            int gc = colBase + tcol*TN + j;
            if (gc < N){
                float b = bias ? bias[gc] : 0.f;
                C[(size_t)gr*N + gc] = acc[i][j] + b;
            }
        }
    }
}

// ---------------- postprocess: gates, RMSNorm B/C, dt/lam/decay ----------------
__global__ void k_post(const float* __restrict__ wB, const float* __restrict__ wC,
                       const float* __restrict__ biasB, const float* __restrict__ biasC,
                       const float* __restrict__ A_log)
{
    const int l = blockIdx.x;
    const int tid = threadIdx.x;         // 256 threads
    const float* row = g_proj + (size_t)l*DPROJ;

    for (int i=tid;i<1024;i+=256){
        float v = row[i];
        g_zsilu[l*1024+i] = v / (1.f + expf(-v));
        float w = row[1024+i];
        g_xsilu[l*1024+i] = w / (1.f + expf(-w));
    }

    __shared__ float pB[8], pC[8];
    float vB = row[2048+tid];
    float vC = row[2304+tid];
    float sB = vB*vB, sC = vC*vC;
#pragma unroll
    for (int o=16;o>0;o>>=1){
        sB += __shfl_xor_sync(0xffffffffu, sB, o);
        sC += __shfl_xor_sync(0xffffffffu, sC, o);
    }
    int wp = tid >> 5;
    if ((tid & 31) == 0){ pB[wp]=sB; pC[wp]=sC; }
    __syncthreads();

    int g = tid >> 6, j = tid & 63;
    float mB = (pB[2*g]+pB[2*g+1]) * (1.f/64.f);
    float mC = (pC[2*g]+pC[2*g+1]) * (1.f/64.f);
    g_Bm[l*256+tid] = vB * rsqrtf(mB + EPSV) * wB[j] + biasB[tid];
    g_Cm[l*256+tid] = vC * rsqrtf(mC + EPSV) * wC[j] + biasC[tid];

    if (tid < GN){
        float dtr = row[2560+tid];
        float dt  = (dtr > 20.f) ? dtr : log1pf(expf(dtr));
        float lam = 1.f/(1.f+expf(-row[2564+tid]));
        float A   = -expf(A_log[tid]);
        g_scal[l*GN+tid] = make_float4(dt, lam, expf(dt*A), 0.f);
    }
}

// ---------------- dt cumsum (4 sequences of 2048): one block, warp per group ----------------
__global__ void k_scan_dt()
{
    int g = threadIdx.x >> 5;
    int lane = threadIdx.x & 31;
    float carry = 0.f;
    for (int b=0;b<64;b++){
        int l = b*32 + lane;
        float v = g_scal[l*GN+g].x;
#pragma unroll
        for (int o=1;o<32;o<<=1){
            float t = __shfl_up_sync(0xffffffffu, v, o);
            if (lane >= o) v += t;
        }
        g_sdt[l*GN+g] = carry + v;
        carry += __shfl_sync(0xffffffffu, v, 31);
    }
}

// ---------------- per-chunk decay products ----------------
__global__ void k_chunkdecay(const float* __restrict__ A_log)
{
    int t = threadIdx.x;
    if (t >= NC*GN) return;
    int c = t >> 2, g = t & 3;
    float A = -expf(A_log[g]);
    float e = g_sdt[(c*CH + CH-1)*GN + g];
    float s = c ? g_sdt[(c*CH - 1)*GN + g] : 0.f;
    g_Dc[t] = expf(A*(e-s));
}

// ---------------- RoPE applied in-place to Bm, Cm ----------------
__global__ void k_rope(const float* __restrict__ theta_log)
{
    int idx = blockIdx.x*256 + threadIdx.x;
    if (idx >= LSEQ*GN*16) return;
    int j = idx & 15;
    int g = (idx >> 4) & 3;
    int l = idx >> 6;
    float th = expf(theta_log[g*16+j]);
    float ang = g_sdt[l*GN+g] * th;
    float cs = cosf(ang), sn = sinf(ang);
    int base = l*256 + g*64 + j*4;  // n=2j -> (2j)*R, n=2j+1 -> (2j+1)*R
#pragma unroll
    for (int r=0;r<2;r++){
        float re = g_Bm[base+r],   im = g_Bm[base+2+r];
        g_Bm[base+r]   = re*cs - im*sn;
        g_Bm[base+2+r] = re*sn + im*cs;
        float re2 = g_Cm[base+r],  im2 = g_Cm[base+2+r];
        g_Cm[base+r]   = re2*cs - im2*sn;
        g_Cm[base+2+r] = re2*sn + im2*cs;
    }
}

// ---------------- x_up = xsilu[L*H,64] @ W_xup[64,128] ----------------
__global__ void k_xup(const float* __restrict__ Wx)
{
    __shared__ float Ws[64][128];
    __shared__ float Xs[16][64];
    int tid = threadIdx.x;  // 256
    for (int i=tid;i<64*128;i+=256) Ws[i>>7][i&127] = Wx[i];
    int m0 = blockIdx.x*16;
    for (int i=tid;i<16*64;i+=256)  Xs[i>>6][i&63]  = g_xsilu[(m0 + (i>>6))*64 + (i&63)];
    __syncthreads();
    int col = (tid & 31)*4;
    int r0  = (tid >> 5)*2;
    float a0c[4]={0,0,0,0}, a1c[4]={0,0,0,0};
#pragma unroll 4
    for (int k=0;k<64;k++){
        float a0 = Xs[r0][k], a1 = Xs[r0+1][k];
        float4 w = *(const float4*)&Ws[k][col];
        a0c[0]+=a0*w.x; a0c[1]+=a0*w.y; a0c[2]+=a0*w.z; a0c[3]+=a0*w.w;
        a1c[0]+=a1*w.x; a1c[1]+=a1*w.y; a1c[2]+=a1*w.z; a1c[3]+=a1*w.w;
    }
#pragma unroll
    for (int j2=0;j2<4;j2++){
        g_xup[(size_t)(m0+r0  )*128 + col + j2] = a0c[j2];
        g_xup[(size_t)(m0+r0+1)*128 + col + j2] = a1c[j2];
    }
}

// ---------------- pass A: chunk-local scan, emit final states ----------------
__global__ void k_passA()
{
    const int c = blockIdx.z, h = blockIdx.y;
    const int p = blockIdx.x*4 + (threadIdx.x >> 5);
    const int n = threadIdx.x & 31;
    const int g = h >> 2;
    const int t0 = c*CH;

    float u_prev = 0.f;
    if (c){
        int t = t0-1;
        float2 B = *(const float2*)&g_Bm[(t*GN+g)*64 + n*2];
        float2 X = *(const float2*)&g_xup[(size_t)(t*HH+h)*128 + p*2];
        float4 s = g_scal[t*GN+g];
        u_prev = s.x*(B.x*X.x + B.y*X.y);
    }
    float hs = 0.f;
#pragma unroll 4
    for (int t=t0; t<t0+CH; t++){
        float2 B = *(const float2*)&g_Bm[(t*GN+g)*64 + n*2];
        float2 X = *(const float2*)&g_xup[(size_t)(t*HH+h)*128 + p*2];
        float4 s = g_scal[t*GN+g];
        float uss = s.x*(B.x*X.x + B.y*X.y);
        float ut  = s.y*uss + (1.f-s.y)*u_prev;
        u_prev = uss;
        hs = hs*s.z + ut;
    }
    g_F[((c*HH+h)*PP+p)*NS + n] = hs;
}

// ---------------- pass B: inter-chunk combine (16-step scan) ----------------
__global__ void k_passB()
{
    int gw = blockIdx.x*8 + (threadIdx.x >> 5);   // 1024 warps total
    int n  = threadIdx.x & 31;
    int h = gw >> 6, p = gw & 63;
    int g = h >> 2;
    float S = 0.f;
#pragma unroll
    for (int c=0;c<NC;c++){
        int idx = ((c*HH+h)*PP+p)*NS + n;
        g_S[idx] = S;
        S = S*g_Dc[c*GN+g] + g_F[idx];
    }
}

// ---------------- pass C: rescan with incoming state, produce y_raw ----------------
__global__ void k_passC()
{
    const int c = blockIdx.z, h = blockIdx.y;
    const int p = blockIdx.x*4 + (threadIdx.x >> 5);
    const int n = threadIdx.x & 31;
    const int g = h >> 2;
    const int t0 = c*CH;

    float u_prev = 0.f;
    if (c){
        int t = t0-1;
        float2 B = *(const float2*)&g_Bm[(t*GN+g)*64 + n*2];
        float2 X = *(const float2*)&g_xup[(size_t)(t*HH+h)*128 + p*2];
        float4 s = g_scal[t*GN+g];
        u_prev = s.x*(B.x*X.x + B.y*X.y);
    }
    float hs = g_S[((c*HH+h)*PP+p)*NS + n];
#pragma unroll 2
    for (int t=t0; t<t0+CH; t++){
        float2 B = *(const float2*)&g_Bm[(t*GN+g)*64 + n*2];
        float2 X = *(const float2*)&g_xup[(size_t)(t*HH+h)*128 + p*2];
        float4 s = g_scal[t*GN+g];
        float uss = s.x*(B.x*X.x + B.y*X.y);
        float ut  = s.y*uss + (1.f-s.y)*u_prev;
        u_prev = uss;
        hs = hs*s.z + ut;

        float2 Cv = *(const float2*)&g_Cm[(t*GN+g)*64 + n*2];
        float y0 = hs*Cv.x, y1 = hs*Cv.y;
#pragma unroll
        for (int o=16;o>0;o>>=1){
            y0 += __shfl_xor_sync(0xffffffffu, y0, o);
            y1 += __shfl_xor_sync(0xffffffffu, y1, o);
        }
        if (n == 0)
            *(float2*)&g_yraw[(size_t)(t*HH+h)*128 + p*2] = make_float2(y0, y1);
    }
}

// ---------------- ydown + skip + z-gate ----------------
__global__ void k_ydown(const float* __restrict__ Wy, const float* __restrict__ Dp)
{
    __shared__ float Ws[128][64];
    __shared__ float Ys[16][128];
    int tid = threadIdx.x;  // 128
    for (int i=tid;i<128*64;i+=128) Ws[i>>6][i&63]  = Wy[i];
    int m0 = blockIdx.x*16;
    for (int i=tid;i<16*128;i+=128) Ys[i>>7][i&127] = g_yraw[(size_t)(m0 + (i>>7))*128 + (i&127)];
    __syncthreads();
    int col = (tid & 15)*4;
    int r0  = (tid >> 4)*2;
    float a0c[4]={0,0,0,0}, a1c[4]={0,0,0,0};
#pragma unroll 4
    for (int k=0;k<128;k++){
        float a0 = Ys[r0][k], a1 = Ys[r0+1][k];
        float4 w = *(const float4*)&Ws[k][col];
        a0c[0]+=a0*w.x; a0c[1]+=a0*w.y; a0c[2]+=a0*w.z; a0c[3]+=a0*w.w;
        a1c[0]+=a1*w.x; a1c[1]+=a1*w.y; a1c[2]+=a1*w.z; a1c[3]+=a1*w.w;
    }
#pragma unroll
    for (int rr=0;rr<2;rr++){
        int m = m0 + r0 + rr;
        int hh = m & 15;
        float dv = Dp[hh];
        float* accp = rr ? a1c : a0c;
#pragma unroll
        for (int j2=0;j2<4;j2++){
            int o = m*64 + col + j2;
            float v = accp[j2] + dv * g_xsilu[o];
            g_y3[o] = v * g_zsilu[o];
        }
    }
}

// ---------------- launch ----------------
extern "C" void kernel_launch(void* const* d_in, const int* in_sizes, int n_in,
                              void* d_out, int out_size)
{
    const float* u        = (const float*)d_in[0];
    const float* W_in     = (const float*)d_in[1];
    const float* b_in     = (const float*)d_in[2];
    const float* W_xup    = (const float*)d_in[3];
    const float* W_ydown  = (const float*)d_in[4];
    const float* A_log    = (const float*)d_in[5];
    const float* theta_log= (const float*)d_in[6];
    const float* D_param  = (const float*)d_in[7];
    const float* wB       = (const float*)d_in[8];
    const float* wC       = (const float*)d_in[9];
    const float* bias_B   = (const float*)d_in[10];
    const float* bias_C   = (const float*)d_in[11];
    const float* W_out    = (const float*)d_in[12];
    float* out = (float*)d_out;

    float *p_proj, *p_y3;
    cudaGetSymbolAddress((void**)&p_proj, g_proj);
    cudaGetSymbolAddress((void**)&p_y3,   g_y3);

    // 1. proj = u @ W_in + b_in   [2048 x 2568, K=512]
    {
        dim3 grid((DPROJ + 127)/128, LSEQ/128);
        k_sgemm<128,128,16,8,8><<<grid, 256>>>(LSEQ, DPROJ, DMODEL, u, W_in, b_in, p_proj);
    }
    // 2. gates / rmsnorm / dt
    k_post<<<LSEQ, 256>>>(wB, wC, bias_B, bias_C, A_log);
    // 3. dt cumsum
    k_scan_dt<<<1, 128>>>();
    // 4. chunk decays
    k_chunkdecay<<<1, 64>>>(A_log);
    // 5. RoPE
    k_rope<<<(LSEQ*GN*16 + 255)/256, 256>>>(theta_log);
    // 6. x_up
    k_xup<<<(LSEQ*HH)/16, 256>>>(W_xup);
    // 7-9. chunked recurrence
    k_passA<<<dim3(16, HH, NC), 128>>>();
    k_passB<<<128, 256>>>();
    k_passC<<<dim3(16, HH, NC), 128>>>();
    // 10. ydown + skip + gate
    k_ydown<<<(LSEQ*HH)/16, 128>>>(W_ydown, D_param);
    // 11. out = y3 @ W_out   [2048 x 512, K=1024]
    {
        dim3 grid(DMODEL/64, LSEQ/64);
        k_sgemm<64,64,16,4,4><<<grid, 256>>>(LSEQ, DMODEL, 1024, p_y3, W_out, nullptr, out);
    }
}

// round 6
// speedup vs baseline: 1.9577x; 1.9577x over previous
#include <cuda_runtime.h>
#include <cuda_bf16.h>
#include <cstdint>

// ---------------- problem dims ----------------
#define LSEQ 2048
#define DMODEL 512
#define DPROJ 2568
#define GN 4          // groups
#define NS 32         // d_state
#define HH 16         // heads
#define PP 64         // head dim
#define NC 16         // chunks
#define CH 128        // chunk len
#define EPSV 1e-5f

// proj row offsets: z[0,1024) x[1024,2048) B[2048,2304) C[2304,2560) dt[2560,2564) lam[2564,2568)

// ---------------- scratch (device globals; no allocs allowed) ----------------
__device__ float  g_proj [LSEQ*DPROJ];
__device__ float  g_zsilu[LSEQ*1024];
__device__ float  g_xsilu[LSEQ*1024];
__device__ float  g_Bm   [LSEQ*GN*64];
__device__ float  g_Cm   [LSEQ*GN*64];
__device__ float4 g_scal [LSEQ*GN];           // (dt, lam, decay, 0)
__device__ float  g_sdt  [LSEQ*GN];
__device__ float  g_Dc   [NC*GN];
__device__ float  g_xup  [LSEQ*HH*128];
__device__ float  g_F    [NC*HH*PP*NS];
__device__ float  g_S    [NC*HH*PP*NS];
__device__ float  g_yraw [LSEQ*HH*128];
__device__ float  g_y3   [LSEQ*1024];

// ---------------- tf32 helpers ----------------
__device__ __forceinline__ void split_tf32(float x, unsigned int& h, unsigned int& l){
    unsigned int xh; asm("cvt.rna.tf32.f32 %0, %1;" : "=r"(xh) : "f"(x));
    float lf = x - __uint_as_float(xh);
    unsigned int xl; asm("cvt.rna.tf32.f32 %0, %1;" : "=r"(xl) : "f"(lf));
    h = xh; l = xl;
}

__device__ __forceinline__ void mma_tf32(float* d, const unsigned int* a, const unsigned int* b){
    asm volatile("mma.sync.aligned.m16n8k8.row.col.f32.tf32.tf32.f32 "
        "{%0,%1,%2,%3}, {%4,%5,%6,%7}, {%8,%9}, {%0,%1,%2,%3};"
        : "+f"(d[0]),"+f"(d[1]),"+f"(d[2]),"+f"(d[3])
        : "r"(a[0]),"r"(a[1]),"r"(a[2]),"r"(a[3]), "r"(b[0]),"r"(b[1]));
}

// ---------------- tensor-core GEMM: C = A[MxK]@B[KxN] (+bias), 3xTF32 split ----------------
// block 128x128, BK=16, 8 warps (4 m x 2 n), warp tile 32x64
__global__ __launch_bounds__(256) void k_gemm_tf32(
    int M, int N, int K,
    const float* __restrict__ A,
    const float* __restrict__ B,
    const float* __restrict__ bias,
    float* __restrict__ C)
{
    const int BM=128, BN=128, BK=16;
    __shared__ unsigned int Ah[16][128+4];
    __shared__ unsigned int Al[16][128+4];
    __shared__ unsigned int Bh[16][128+4];
    __shared__ unsigned int Bl[16][128+4];

    const int tid  = threadIdx.x;
    const int lane = tid & 31;
    const int warp = tid >> 5;
    const int warpM = warp >> 1;       // 0..3 -> 32 rows each
    const int warpN = warp & 1;        // 0..1 -> 64 cols each
    const int rowBase = blockIdx.y * BM;
    const int colBase = blockIdx.x * BN;

    float acc[2][8][4];
#pragma unroll
    for (int t=0;t<2;t++)
#pragma unroll
        for (int j=0;j<8;j++)
#pragma unroll
            for (int q=0;q<4;q++) acc[t][j][q]=0.f;

    for (int k0=0;k0<K;k0+=BK){
        // stage A tile (128x16) as hi/lo tf32
#pragma unroll
        for (int i=tid;i<BM*BK/4;i+=256){
            int r  = i >> 2;           // BK/4 = 4
            int c4 = (i & 3) * 4;
            int gr = rowBase + r;
            float4 v = make_float4(0,0,0,0);
            if (gr < M) v = *(const float4*)&A[(size_t)gr*K + k0 + c4];
            unsigned int h,l;
            split_tf32(v.x,h,l); Ah[c4+0][r]=h; Al[c4+0][r]=l;
            split_tf32(v.y,h,l); Ah[c4+1][r]=h; Al[c4+1][r]=l;
            split_tf32(v.z,h,l); Ah[c4+2][r]=h; Al[c4+2][r]=l;
            split_tf32(v.w,h,l); Ah[c4+3][r]=h; Al[c4+3][r]=l;
        }
        // stage B tile (16x128) as hi/lo tf32
#pragma unroll
        for (int i=tid;i<BK*BN/4;i+=256){
            int r  = i >> 5;           // BN/4 = 32
            int c4 = (i & 31) * 4;
            int gc = colBase + c4;
            float4 v = make_float4(0,0,0,0);
            if (gc < N) v = *(const float4*)&B[(size_t)(k0+r)*N + gc];
            unsigned int h,l;
            split_tf32(v.x,h,l); Bh[r][c4+0]=h; Bl[r][c4+0]=l;
            split_tf32(v.y,h,l); Bh[r][c4+1]=h; Bl[r][c4+1]=l;
            split_tf32(v.z,h,l); Bh[r][c4+2]=h; Bl[r][c4+2]=l;
            split_tf32(v.w,h,l); Bh[r][c4+3]=h; Bl[r][c4+3]=l;
        }
        __syncthreads();

#pragma unroll
        for (int kk=0;kk<2;kk++){
            unsigned int ah[2][4], al[2][4];
#pragma unroll
            for (int t=0;t<2;t++){
                int r = warpM*32 + t*16 + (lane>>2);
                int c = kk*8 + (lane&3);
                ah[t][0]=Ah[c  ][r  ]; al[t][0]=Al[c  ][r  ];
                ah[t][1]=Ah[c  ][r+8]; al[t][1]=Al[c  ][r+8];
                ah[t][2]=Ah[c+4][r  ]; al[t][2]=Al[c+4][r  ];
                ah[t][3]=Ah[c+4][r+8]; al[t][3]=Al[c+4][r+8];
            }
            unsigned int bh[8][2], bl[8][2];
#pragma unroll
            for (int j=0;j<8;j++){
                int cb = warpN*64 + j*8 + (lane>>2);
                int rb = kk*8 + (lane&3);
                bh[j][0]=Bh[rb  ][cb]; bl[j][0]=Bl[rb  ][cb];
                bh[j][1]=Bh[rb+4][cb]; bl[j][1]=Bl[rb+4][cb];
            }
#pragma unroll
            for (int t=0;t<2;t++)
#pragma unroll
                for (int j=0;j<8;j++){
                    mma_tf32(acc[t][j], ah[t], bh[j]);
                    mma_tf32(acc[t][j], ah[t], bl[j]);
                    mma_tf32(acc[t][j], al[t], bh[j]);
                }
        }
        __syncthreads();
    }

    // epilogue
#pragma unroll
    for (int t=0;t<2;t++){
#pragma unroll
        for (int j=0;j<8;j++){
            int row = rowBase + warpM*32 + t*16 + (lane>>2);
            int col = colBase + warpN*64 + j*8 + 2*(lane&3);
            if (col < N){
                float b0 = bias ? bias[col] : 0.f;
                float b1 = (bias && col+1<N) ? bias[col+1] : 0.f;
                if (row < M){
                    C[(size_t)row*N + col] = acc[t][j][0] + b0;
                    if (col+1 < N) C[(size_t)row*N + col+1] = acc[t][j][1] + b1;
                }
                if (row+8 < M){
                    C[(size_t)(row+8)*N + col] = acc[t][j][2] + b0;
                    if (col+1 < N) C[(size_t)(row+8)*N + col+1] = acc[t][j][3] + b1;
                }
            }
        }
    }
}

// ---------------- postprocess: gates, RMSNorm B/C, dt/lam/decay ----------------
__global__ void k_post(const float* __restrict__ wB, const float* __restrict__ wC,
                       const float* __restrict__ biasB, const float* __restrict__ biasC,
                       const float* __restrict__ A_log)
{
    const int l = blockIdx.x;
    const int tid = threadIdx.x;         // 256 threads
    const float* row = g_proj + (size_t)l*DPROJ;

    for (int i=tid;i<1024;i+=256){
        float v = row[i];
        g_zsilu[l*1024+i] = v / (1.f + expf(-v));
        float w = row[1024+i];
        g_xsilu[l*1024+i] = w / (1.f + expf(-w));
    }

    __shared__ float pB[8], pC[8];
    float vB = row[2048+tid];
    float vC = row[2304+tid];
    float sB = vB*vB, sC = vC*vC;
#pragma unroll
    for (int o=16;o>0;o>>=1){
        sB += __shfl_xor_sync(0xffffffffu, sB, o);
        sC += __shfl_xor_sync(0xffffffffu, sC, o);
    }
    int wp = tid >> 5;
    if ((tid & 31) == 0){ pB[wp]=sB; pC[wp]=sC; }
    __syncthreads();

    int g = tid >> 6, j = tid & 63;
    float mB = (pB[2*g]+pB[2*g+1]) * (1.f/64.f);
    float mC = (pC[2*g]+pC[2*g+1]) * (1.f/64.f);
    g_Bm[l*256+tid] = vB * rsqrtf(mB + EPSV) * wB[j] + biasB[tid];
    g_Cm[l*256+tid] = vC * rsqrtf(mC + EPSV) * wC[j] + biasC[tid];

    if (tid < GN){
        float dtr = row[2560+tid];
        float dt  = (dtr > 20.f) ? dtr : log1pf(expf(dtr));
        float lam = 1.f/(1.f+expf(-row[2564+tid]));
        float A   = -expf(A_log[tid]);
        g_scal[l*GN+tid] = make_float4(dt, lam, expf(dt*A), 0.f);
    }
}

// ---------------- dt cumsum (4 sequences of 2048): one block, warp per group ----------------
__global__ void k_scan_dt()
{
    int g = threadIdx.x >> 5;
    int lane = threadIdx.x & 31;
    float carry = 0.f;
    for (int b=0;b<64;b++){
        int l = b*32 + lane;
        float v = g_scal[l*GN+g].x;
#pragma unroll
        for (int o=1;o<32;o<<=1){
            float t = __shfl_up_sync(0xffffffffu, v, o);
            if (lane >= o) v += t;
        }
        g_sdt[l*GN+g] = carry + v;
        carry += __shfl_sync(0xffffffffu, v, 31);
    }
}

// ---------------- per-chunk decay products ----------------
__global__ void k_chunkdecay(const float* __restrict__ A_log)
{
    int t = threadIdx.x;
    if (t >= NC*GN) return;
    int c = t >> 2, g = t & 3;
    float A = -expf(A_log[g]);
    float e = g_sdt[(c*CH + CH-1)*GN + g];
    float s = c ? g_sdt[(c*CH - 1)*GN + g] : 0.f;
    g_Dc[t] = expf(A*(e-s));
}

// ---------------- RoPE applied in-place to Bm, Cm ----------------
__global__ void k_rope(const float* __restrict__ theta_log)
{
    int idx = blockIdx.x*256 + threadIdx.x;
    if (idx >= LSEQ*GN*16) return;
    int j = idx & 15;
    int g = (idx >> 4) & 3;
    int l = idx >> 6;
    float th = expf(theta_log[g*16+j]);
    float ang = g_sdt[l*GN+g] * th;
    float cs = cosf(ang), sn = sinf(ang);
    int base = l*256 + g*64 + j*4;
#pragma unroll
    for (int r=0;r<2;r++){
        float re = g_Bm[base+r],   im = g_Bm[base+2+r];
        g_Bm[base+r]   = re*cs - im*sn;
        g_Bm[base+2+r] = re*sn + im*cs;
        float re2 = g_Cm[base+r],  im2 = g_Cm[base+2+r];
        g_Cm[base+r]   = re2*cs - im2*sn;
        g_Cm[base+2+r] = re2*sn + im2*cs;
    }
}

// ---------------- x_up = xsilu[L*H,64] @ W_xup[64,128] ----------------
__global__ void k_xup(const float* __restrict__ Wx)
{
    __shared__ float Ws[64][128];
    __shared__ float Xs[16][64];
    int tid = threadIdx.x;  // 256
    for (int i=tid;i<64*128;i+=256) Ws[i>>7][i&127] = Wx[i];
    int m0 = blockIdx.x*16;
    for (int i=tid;i<16*64;i+=256)  Xs[i>>6][i&63]  = g_xsilu[(m0 + (i>>6))*64 + (i&63)];
    __syncthreads();
    int col = (tid & 31)*4;
    int r0  = (tid >> 5)*2;
    float a0c[4]={0,0,0,0}, a1c[4]={0,0,0,0};
#pragma unroll 4
    for (int k=0;k<64;k++){
        float a0 = Xs[r0][k], a1 = Xs[r0+1][k];
        float4 w = *(const float4*)&Ws[k][col];
        a0c[0]+=a0*w.x; a0c[1]+=a0*w.y; a0c[2]+=a0*w.z; a0c[3]+=a0*w.w;
        a1c[0]+=a1*w.x; a1c[1]+=a1*w.y; a1c[2]+=a1*w.z; a1c[3]+=a1*w.w;
    }
#pragma unroll
    for (int j2=0;j2<4;j2++){
        g_xup[(size_t)(m0+r0  )*128 + col + j2] = a0c[j2];
        g_xup[(size_t)(m0+r0+1)*128 + col + j2] = a1c[j2];
    }
}

// ---------------- pass A: chunk-local scan, emit final states ----------------
__global__ void k_passA()
{
    const int c = blockIdx.z, h = blockIdx.y;
    const int p = blockIdx.x*4 + (threadIdx.x >> 5);
    const int n = threadIdx.x & 31;
    const int g = h >> 2;
    const int t0 = c*CH;

    float u_prev = 0.f;
    if (c){
        int t = t0-1;
        float2 B = *(const float2*)&g_Bm[(t*GN+g)*64 + n*2];
        float2 X = *(const float2*)&g_xup[(size_t)(t*HH+h)*128 + p*2];
        float4 s = g_scal[t*GN+g];
        u_prev = s.x*(B.x*X.x + B.y*X.y);
    }
    float hs = 0.f;
#pragma unroll 4
    for (int t=t0; t<t0+CH; t++){
        float2 B = *(const float2*)&g_Bm[(t*GN+g)*64 + n*2];
        float2 X = *(const float2*)&g_xup[(size_t)(t*HH+h)*128 + p*2];
        float4 s = g_scal[t*GN+g];
        float uss = s.x*(B.x*X.x + B.y*X.y);
        float ut  = s.y*uss + (1.f-s.y)*u_prev;
        u_prev = uss;
        hs = hs*s.z + ut;
    }
    g_F[((c*HH+h)*PP+p)*NS + n] = hs;
}

// ---------------- pass B: inter-chunk combine (16-step scan) ----------------
__global__ void k_passB()
{
    int gw = blockIdx.x*8 + (threadIdx.x >> 5);   // 1024 warps total
    int n  = threadIdx.x & 31;
    int h = gw >> 6, p = gw & 63;
    int g = h >> 2;
    float S = 0.f;
#pragma unroll
    for (int c=0;c<NC;c++){
        int idx = ((c*HH+h)*PP+p)*NS + n;
        g_S[idx] = S;
        S = S*g_Dc[c*GN+g] + g_F[idx];
    }
}

// ---------------- pass C: rescan with incoming state, produce y_raw ----------------
__global__ void k_passC()
{
    const int c = blockIdx.z, h = blockIdx.y;
    const int p = blockIdx.x*4 + (threadIdx.x >> 5);
    const int n = threadIdx.x & 31;
    const int g = h >> 2;
    const int t0 = c*CH;

    float u_prev = 0.f;
    if (c){
        int t = t0-1;
        float2 B = *(const float2*)&g_Bm[(t*GN+g)*64 + n*2];
        float2 X = *(const float2*)&g_xup[(size_t)(t*HH+h)*128 + p*2];
        float4 s = g_scal[t*GN+g];
        u_prev = s.x*(B.x*X.x + B.y*X.y);
    }
    float hs = g_S[((c*HH+h)*PP+p)*NS + n];
#pragma unroll 2
    for (int t=t0; t<t0+CH; t++){
        float2 B = *(const float2*)&g_Bm[(t*GN+g)*64 + n*2];
        float2 X = *(const float2*)&g_xup[(size_t)(t*HH+h)*128 + p*2];
        float4 s = g_scal[t*GN+g];
        float uss = s.x*(B.x*X.x + B.y*X.y);
        float ut  = s.y*uss + (1.f-s.y)*u_prev;
        u_prev = uss;
        hs = hs*s.z + ut;

        float2 Cv = *(const float2*)&g_Cm[(t*GN+g)*64 + n*2];
        float y0 = hs*Cv.x, y1 = hs*Cv.y;
#pragma unroll
        for (int o=16;o>0;o>>=1){
            y0 += __shfl_xor_sync(0xffffffffu, y0, o);
            y1 += __shfl_xor_sync(0xffffffffu, y1, o);
        }
        if (n == 0)
            *(float2*)&g_yraw[(size_t)(t*HH+h)*128 + p*2] = make_float2(y0, y1);
    }
}

// ---------------- ydown + skip + z-gate ----------------
__global__ void k_ydown(const float* __restrict__ Wy, const float* __restrict__ Dp)
{
    __shared__ float Ws[128][64];
    __shared__ float Ys[16][128];
    int tid = threadIdx.x;  // 128
    for (int i=tid;i<128*64;i+=128) Ws[i>>6][i&63]  = Wy[i];
    int m0 = blockIdx.x*16;
    for (int i=tid;i<16*128;i+=128) Ys[i>>7][i&127] = g_yraw[(size_t)(m0 + (i>>7))*128 + (i&127)];
    __syncthreads();
    int col = (tid & 15)*4;
    int r0  = (tid >> 4)*2;
    float a0c[4]={0,0,0,0}, a1c[4]={0,0,0,0};
#pragma unroll 4
    for (int k=0;k<128;k++){
        float a0 = Ys[r0][k], a1 = Ys[r0+1][k];
        float4 w = *(const float4*)&Ws[k][col];
        a0c[0]+=a0*w.x; a0c[1]+=a0*w.y; a0c[2]+=a0*w.z; a0c[3]+=a0*w.w;
        a1c[0]+=a1*w.x; a1c[1]+=a1*w.y; a1c[2]+=a1*w.z; a1c[3]+=a1*w.w;
    }
#pragma unroll
    for (int rr=0;rr<2;rr++){
        int m = m0 + r0 + rr;
        int hh = m & 15;
        float dv = Dp[hh];
        float* accp = rr ? a1c : a0c;
#pragma unroll
        for (int j2=0;j2<4;j2++){
            int o = m*64 + col + j2;
            float v = accp[j2] + dv * g_xsilu[o];
            g_y3[o] = v * g_zsilu[o];
        }
    }
}

// ---------------- launch ----------------
extern "C" void kernel_launch(void* const* d_in, const int* in_sizes, int n_in,
                              void* d_out, int out_size)
{
    const float* u        = (const float*)d_in[0];
    const float* W_in     = (const float*)d_in[1];
    const float* b_in     = (const float*)d_in[2];
    const float* W_xup    = (const float*)d_in[3];
    const float* W_ydown  = (const float*)d_in[4];
    const float* A_log    = (const float*)d_in[5];
    const float* theta_log= (const float*)d_in[6];
    const float* D_param  = (const float*)d_in[7];
    const float* wB       = (const float*)d_in[8];
    const float* wC       = (const float*)d_in[9];
    const float* bias_B   = (const float*)d_in[10];
    const float* bias_C   = (const float*)d_in[11];
    const float* W_out    = (const float*)d_in[12];
    float* out = (float*)d_out;

    float *p_proj, *p_y3;
    cudaGetSymbolAddress((void**)&p_proj, g_proj);
    cudaGetSymbolAddress((void**)&p_y3,   g_y3);

    // 1. proj = u @ W_in + b_in   [2048 x 2568, K=512]   tensor cores, 3xTF32
    {
        dim3 grid((DPROJ + 127)/128, LSEQ/128);
        k_gemm_tf32<<<grid, 256>>>(LSEQ, DPROJ, DMODEL, u, W_in, b_in, p_proj);
    }
    // 2. gates / rmsnorm / dt
    k_post<<<LSEQ, 256>>>(wB, wC, bias_B, bias_C, A_log);
    // 3. dt cumsum
    k_scan_dt<<<1, 128>>>();
    // 4. chunk decays
    k_chunkdecay<<<1, 64>>>(A_log);
    // 5. RoPE
    k_rope<<<(LSEQ*GN*16 + 255)/256, 256>>>(theta_log);
    // 6. x_up
    k_xup<<<(LSEQ*HH)/16, 256>>>(W_xup);
    // 7-9. chunked recurrence
    k_passA<<<dim3(16, HH, NC), 128>>>();
    k_passB<<<128, 256>>>();
    k_passC<<<dim3(16, HH, NC), 128>>>();
    // 10. ydown + skip + gate
    k_ydown<<<(LSEQ*HH)/16, 128>>>(W_ydown, D_param);
    // 11. out = y3 @ W_out   [2048 x 512, K=1024]   tensor cores, 3xTF32
    {
        dim3 grid(DMODEL/128, LSEQ/128);
        k_gemm_tf32<<<grid, 256>>>(LSEQ, DMODEL, 1024, p_y3, W_out, nullptr, out);
    }
}

// round 7
// speedup vs baseline: 2.4752x; 1.2643x over previous
#include <cuda_runtime.h>
#include <cuda_bf16.h>
#include <cstdint>

// ---------------- problem dims ----------------
#define LSEQ 2048
#define DMODEL 512
#define DPROJ 2568
#define GN 4          // groups
#define NS 32         // d_state
#define HH 16         // heads
#define PP 64         // head dim
#define NC 16         // chunks
#define CH 128        // chunk len
#define EPSV 1e-5f

// proj row offsets: z[0,1024) x[1024,2048) B[2048,2304) C[2304,2560) dt[2560,2564) lam[2564,2568)

// ---------------- scratch (device globals; no allocs allowed) ----------------
__device__ float  g_proj [LSEQ*DPROJ];
__device__ float  g_zsilu[LSEQ*1024];
__device__ float  g_xsilu[LSEQ*1024];
__device__ float  g_Bm   [LSEQ*GN*64];
__device__ float  g_Cm   [LSEQ*GN*64];
__device__ float4 g_scal [LSEQ*GN];           // (dt, lam, decay, 0)
__device__ float  g_sdt  [LSEQ*GN];
__device__ float  g_Dc   [NC*GN];
__device__ float  g_xup  [LSEQ*HH*128];
__device__ float  g_F    [NC*HH*PP*NS];
__device__ float  g_S    [NC*HH*PP*NS];
__device__ float  g_yraw [LSEQ*HH*128];
__device__ float  g_y3   [LSEQ*1024];

// ---------------- bf16-split helpers ----------------
// pack two consecutive-k values (k even -> low half, k odd -> high half),
// hi = bf16(x), lo = bf16(x - hi). 3-product MMA drops lo*lo (~2^-18 rel).
__device__ __forceinline__ void split2(float x, float y, unsigned int& h, unsigned int& l){
    __nv_bfloat162 H = __floats2bfloat162_rn(x, y);
    float rx = x - __bfloat162float(H.x);
    float ry = y - __bfloat162float(H.y);
    __nv_bfloat162 L = __floats2bfloat162_rn(rx, ry);
    h = *reinterpret_cast<unsigned int*>(&H);
    l = *reinterpret_cast<unsigned int*>(&L);
}

__device__ __forceinline__ void mma_bf16(float* d, const unsigned int* a, const unsigned int* b){
    asm volatile("mma.sync.aligned.m16n8k16.row.col.f32.bf16.bf16.f32 "
        "{%0,%1,%2,%3}, {%4,%5,%6,%7}, {%8,%9}, {%0,%1,%2,%3};"
        : "+f"(d[0]),"+f"(d[1]),"+f"(d[2]),"+f"(d[3])
        : "r"(a[0]),"r"(a[1]),"r"(a[2]),"r"(a[3]), "r"(b[0]),"r"(b[1]));
}

// ---------------- tensor-core GEMM: C = A[MxK]@B[KxN] (+bias), 3x bf16 split ----------------
// block 128 x BN, BK=16, 8 warps (4 m x 2 n). Requires M%128==0, K%16==0, N%4==0.
template<int BN>
__global__ __launch_bounds__(256) void k_gemm_bf16s(
    int M, int N, int K,
    const float* __restrict__ A,
    const float* __restrict__ B,
    const float* __restrict__ bias,
    float* __restrict__ C)
{
    const int BM=128;
    const int JW  = BN/16;     // n-subtiles per warp
    const int NB4 = BN/4;      // B staging columns groups
    const int NBITEMS = 8*NB4; // B staging items (k-pair rows x col4 groups)

    __shared__ unsigned int Ah[8][BM+8];
    __shared__ unsigned int Al[8][BM+8];
    __shared__ unsigned int Bh[8][BN+8];
    __shared__ unsigned int Bl[8][BN+8];

    const int tid  = threadIdx.x;
    const int lane = tid & 31;
    const int warp = tid >> 5;
    const int warpM = warp >> 1;
    const int warpN = warp & 1;
    const int rowBase = blockIdx.y * BM;
    const int colBase = blockIdx.x * BN;
    const int kq = lane & 3;

    float acc[2][JW][4];
#pragma unroll
    for (int t=0;t<2;t++)
#pragma unroll
        for (int j=0;j<JW;j++)
#pragma unroll
            for (int q=0;q<4;q++) acc[t][j][q]=0.f;

    // staging coords
    const int ar0 = tid >> 2;          // 0..63
    const int ac0 = (tid & 3) * 4;     // 0,4,8,12
    const int br2 = tid / NB4;         // k-pair row for B item
    const int bcc = (tid % NB4) * 4;
    const bool bact = (tid < NBITEMS);

    float4 pa0, pa1, pb0, pb1;

#define LOADT(kk0) { \
    pa0 = *(const float4*)&A[(size_t)(rowBase+ar0   )*K + (kk0) + ac0]; \
    pa1 = *(const float4*)&A[(size_t)(rowBase+ar0+64)*K + (kk0) + ac0]; \
    if (bact){ int gc = colBase + bcc; \
        if (gc < N){ \
            pb0 = *(const float4*)&B[(size_t)((kk0)+2*br2  )*N + gc]; \
            pb1 = *(const float4*)&B[(size_t)((kk0)+2*br2+1)*N + gc]; \
        } else { pb0 = make_float4(0,0,0,0); pb1 = pb0; } } }

#define STORET() { \
    split2(pa0.x, pa0.y, Ah[ac0/2  ][ar0   ], Al[ac0/2  ][ar0   ]); \
    split2(pa0.z, pa0.w, Ah[ac0/2+1][ar0   ], Al[ac0/2+1][ar0   ]); \
    split2(pa1.x, pa1.y, Ah[ac0/2  ][ar0+64], Al[ac0/2  ][ar0+64]); \
    split2(pa1.z, pa1.w, Ah[ac0/2+1][ar0+64], Al[ac0/2+1][ar0+64]); \
    if (bact){ \
        split2(pb0.x, pb1.x, Bh[br2][bcc+0], Bl[br2][bcc+0]); \
        split2(pb0.y, pb1.y, Bh[br2][bcc+1], Bl[br2][bcc+1]); \
        split2(pb0.z, pb1.z, Bh[br2][bcc+2], Bl[br2][bcc+2]); \
        split2(pb0.w, pb1.w, Bh[br2][bcc+3], Bl[br2][bcc+3]); } }

    LOADT(0);
    STORET();
    __syncthreads();

    for (int k0=0; k0<K; k0+=16){
        const bool more = (k0+16 < K);
        if (more){ LOADT(k0+16); }

        // fragment loads
        unsigned int ah[2][4], alr[2][4];
#pragma unroll
        for (int t=0;t<2;t++){
            int r = warpM*32 + t*16 + (lane>>2);
            ah[t][0]=Ah[kq  ][r];   alr[t][0]=Al[kq  ][r];
            ah[t][1]=Ah[kq  ][r+8]; alr[t][1]=Al[kq  ][r+8];
            ah[t][2]=Ah[kq+4][r];   alr[t][2]=Al[kq+4][r];
            ah[t][3]=Ah[kq+4][r+8]; alr[t][3]=Al[kq+4][r+8];
        }
        unsigned int bh[JW][2], blr[JW][2];
#pragma unroll
        for (int j=0;j<JW;j++){
            int cb = warpN*(BN/2) + j*8 + (lane>>2);
            bh[j][0]=Bh[kq  ][cb];  blr[j][0]=Bl[kq  ][cb];
            bh[j][1]=Bh[kq+4][cb];  blr[j][1]=Bl[kq+4][cb];
        }
#pragma unroll
        for (int t=0;t<2;t++)
#pragma unroll
            for (int j=0;j<JW;j++){
                mma_bf16(acc[t][j], ah[t],  bh[j]);
                mma_bf16(acc[t][j], ah[t],  blr[j]);
                mma_bf16(acc[t][j], alr[t], bh[j]);
            }
        __syncthreads();
        if (more){
            STORET();
            __syncthreads();
        }
    }

    // epilogue
#pragma unroll
    for (int t=0;t<2;t++){
#pragma unroll
        for (int j=0;j<JW;j++){
            int row = rowBase + warpM*32 + t*16 + (lane>>2);
            int col = colBase + warpN*(BN/2) + j*8 + 2*(lane&3);
            if (col < N){
                float b0 = bias ? bias[col] : 0.f;
                float b1 = (bias && col+1<N) ? bias[col+1] : 0.f;
                C[(size_t)row*N + col] = acc[t][j][0] + b0;
                if (col+1 < N) C[(size_t)row*N + col+1] = acc[t][j][1] + b1;
                C[(size_t)(row+8)*N + col] = acc[t][j][2] + b0;
                if (col+1 < N) C[(size_t)(row+8)*N + col+1] = acc[t][j][3] + b1;
            }
        }
    }
#undef LOADT
#undef STORET
}

// ---------------- postprocess: gates, RMSNorm B/C, dt/lam/decay ----------------
__global__ void k_post(const float* __restrict__ wB, const float* __restrict__ wC,
                       const float* __restrict__ biasB, const float* __restrict__ biasC,
                       const float* __restrict__ A_log)
{
    const int l = blockIdx.x;
    const int tid = threadIdx.x;         // 256 threads
    const float* row = g_proj + (size_t)l*DPROJ;

    for (int i=tid;i<1024;i+=256){
        float v = row[i];
        g_zsilu[l*1024+i] = v / (1.f + expf(-v));
        float w = row[1024+i];
        g_xsilu[l*1024+i] = w / (1.f + expf(-w));
    }

    __shared__ float pB[8], pC[8];
    float vB = row[2048+tid];
    float vC = row[2304+tid];
    float sB = vB*vB, sC = vC*vC;
#pragma unroll
    for (int o=16;o>0;o>>=1){
        sB += __shfl_xor_sync(0xffffffffu, sB, o);
        sC += __shfl_xor_sync(0xffffffffu, sC, o);
    }
    int wp = tid >> 5;
    if ((tid & 31) == 0){ pB[wp]=sB; pC[wp]=sC; }
    __syncthreads();

    int g = tid >> 6, j = tid & 63;
    float mB = (pB[2*g]+pB[2*g+1]) * (1.f/64.f);
    float mC = (pC[2*g]+pC[2*g+1]) * (1.f/64.f);
    g_Bm[l*256+tid] = vB * rsqrtf(mB + EPSV) * wB[j] + biasB[tid];
    g_Cm[l*256+tid] = vC * rsqrtf(mC + EPSV) * wC[j] + biasC[tid];

    if (tid < GN){
        float dtr = row[2560+tid];
        float dt  = (dtr > 20.f) ? dtr : log1pf(expf(dtr));
        float lam = 1.f/(1.f+expf(-row[2564+tid]));
        float A   = -expf(A_log[tid]);
        g_scal[l*GN+tid] = make_float4(dt, lam, expf(dt*A), 0.f);
    }
}

// ---------------- dt cumsum (4 sequences of 2048) + per-chunk decays ----------------
__global__ void k_scan_dt(const float* __restrict__ A_log)
{
    int g = threadIdx.x >> 5;
    int lane = threadIdx.x & 31;
    float carry = 0.f;
    for (int b=0;b<64;b++){
        int l = b*32 + lane;
        float v = g_scal[l*GN+g].x;
#pragma unroll
        for (int o=1;o<32;o<<=1){
            float t = __shfl_up_sync(0xffffffffu, v, o);
            if (lane >= o) v += t;
        }
        g_sdt[l*GN+g] = carry + v;
        carry += __shfl_sync(0xffffffffu, v, 31);
    }
    __syncthreads();
    int t = threadIdx.x;
    if (t < NC*GN){
        int c = t >> 2, gg = t & 3;
        float A = -expf(A_log[gg]);
        float e = g_sdt[(c*CH + CH-1)*GN + gg];
        float s = c ? g_sdt[(c*CH - 1)*GN + gg] : 0.f;
        g_Dc[t] = expf(A*(e-s));
    }
}

// ---------------- RoPE applied in-place to Bm, Cm ----------------
__global__ void k_rope(const float* __restrict__ theta_log)
{
    int idx = blockIdx.x*256 + threadIdx.x;
    if (idx >= LSEQ*GN*16) return;
    int j = idx & 15;
    int g = (idx >> 4) & 3;
    int l = idx >> 6;
    float th = expf(theta_log[g*16+j]);
    float ang = g_sdt[l*GN+g] * th;
    float cs = cosf(ang), sn = sinf(ang);
    int base = l*256 + g*64 + j*4;
#pragma unroll
    for (int r=0;r<2;r++){
        float re = g_Bm[base+r],   im = g_Bm[base+2+r];
        g_Bm[base+r]   = re*cs - im*sn;
        g_Bm[base+2+r] = re*sn + im*cs;
        float re2 = g_Cm[base+r],  im2 = g_Cm[base+2+r];
        g_Cm[base+r]   = re2*cs - im2*sn;
        g_Cm[base+2+r] = re2*sn + im2*cs;
    }
}

// ---------------- x_up = xsilu[L*H,64] @ W_xup[64,128] ----------------
__global__ void k_xup(const float* __restrict__ Wx)
{
    __shared__ float Ws[64][128];
    __shared__ float Xs[16][64];
    int tid = threadIdx.x;  // 256
    for (int i=tid;i<64*128;i+=256) Ws[i>>7][i&127] = Wx[i];
    int m0 = blockIdx.x*16;
    for (int i=tid;i<16*64;i+=256)  Xs[i>>6][i&63]  = g_xsilu[(m0 + (i>>6))*64 + (i&63)];
    __syncthreads();
    int col = (tid & 31)*4;
    int r0  = (tid >> 5)*2;
    float a0c[4]={0,0,0,0}, a1c[4]={0,0,0,0};
#pragma unroll 4
    for (int k=0;k<64;k++){
        float a0 = Xs[r0][k], a1 = Xs[r0+1][k];
        float4 w = *(const float4*)&Ws[k][col];
        a0c[0]+=a0*w.x; a0c[1]+=a0*w.y; a0c[2]+=a0*w.z; a0c[3]+=a0*w.w;
        a1c[0]+=a1*w.x; a1c[1]+=a1*w.y; a1c[2]+=a1*w.z; a1c[3]+=a1*w.w;
    }
#pragma unroll
    for (int j2=0;j2<4;j2++){
        g_xup[(size_t)(m0+r0  )*128 + col + j2] = a0c[j2];
        g_xup[(size_t)(m0+r0+1)*128 + col + j2] = a1c[j2];
    }
}

// ---------------- pass A: chunk-local scan, emit final states ----------------
__global__ void k_passA()
{
    const int c = blockIdx.z, h = blockIdx.y;
    const int p = blockIdx.x*4 + (threadIdx.x >> 5);
    const int n = threadIdx.x & 31;
    const int g = h >> 2;
    const int t0 = c*CH;

    float u_prev = 0.f;
    if (c){
        int t = t0-1;
        float2 B = *(const float2*)&g_Bm[(t*GN+g)*64 + n*2];
        float2 X = *(const float2*)&g_xup[(size_t)(t*HH+h)*128 + p*2];
        float4 s = g_scal[t*GN+g];
        u_prev = s.x*(B.x*X.x + B.y*X.y);
    }
    float hs = 0.f;
#pragma unroll 4
    for (int t=t0; t<t0+CH; t++){
        float2 B = *(const float2*)&g_Bm[(t*GN+g)*64 + n*2];
        float2 X = *(const float2*)&g_xup[(size_t)(t*HH+h)*128 + p*2];
        float4 s = g_scal[t*GN+g];
        float uss = s.x*(B.x*X.x + B.y*X.y);
        float ut  = s.y*uss + (1.f-s.y)*u_prev;
        u_prev = uss;
        hs = hs*s.z + ut;
    }
    g_F[((c*HH+h)*PP+p)*NS + n] = hs;
}

// ---------------- pass B: inter-chunk combine (16-step scan) ----------------
__global__ void k_passB()
{
    int gw = blockIdx.x*8 + (threadIdx.x >> 5);   // 1024 warps total
    int n  = threadIdx.x & 31;
    int h = gw >> 6, p = gw & 63;
    int g = h >> 2;
    float S = 0.f;
#pragma unroll
    for (int c=0;c<NC;c++){
        int idx = ((c*HH+h)*PP+p)*NS + n;
        g_S[idx] = S;
        S = S*g_Dc[c*GN+g] + g_F[idx];
    }
}

// ---------------- pass C: rescan with incoming state, produce y_raw ----------------
__global__ void k_passC()
{
    const int c = blockIdx.z, h = blockIdx.y;
    const int p = blockIdx.x*4 + (threadIdx.x >> 5);
    const int n = threadIdx.x & 31;
    const int g = h >> 2;
    const int t0 = c*CH;

    float u_prev = 0.f;
    if (c){
        int t = t0-1;
        float2 B = *(const float2*)&g_Bm[(t*GN+g)*64 + n*2];
        float2 X = *(const float2*)&g_xup[(size_t)(t*HH+h)*128 + p*2];
        float4 s = g_scal[t*GN+g];
        u_prev = s.x*(B.x*X.x + B.y*X.y);
    }
    float hs = g_S[((c*HH+h)*PP+p)*NS + n];
#pragma unroll 2
    for (int t=t0; t<t0+CH; t++){
        float2 B = *(const float2*)&g_Bm[(t*GN+g)*64 + n*2];
        float2 X = *(const float2*)&g_xup[(size_t)(t*HH+h)*128 + p*2];
        float4 s = g_scal[t*GN+g];
        float uss = s.x*(B.x*X.x + B.y*X.y);
        float ut  = s.y*uss + (1.f-s.y)*u_prev;
        u_prev = uss;
        hs = hs*s.z + ut;

        float2 Cv = *(const float2*)&g_Cm[(t*GN+g)*64 + n*2];
        float y0 = hs*Cv.x, y1 = hs*Cv.y;
#pragma unroll
        for (int o=16;o>0;o>>=1){
            y0 += __shfl_xor_sync(0xffffffffu, y0, o);
            y1 += __shfl_xor_sync(0xffffffffu, y1, o);
        }
        if (n == 0)
            *(float2*)&g_yraw[(size_t)(t*HH+h)*128 + p*2] = make_float2(y0, y1);
    }
}

// ---------------- ydown + skip + z-gate ----------------
__global__ void k_ydown(const float* __restrict__ Wy, const float* __restrict__ Dp)
{
    __shared__ float Ws[128][64];
    __shared__ float Ys[16][128];
    int tid = threadIdx.x;  // 128
    for (int i=tid;i<128*64;i+=128) Ws[i>>6][i&63]  = Wy[i];
    int m0 = blockIdx.x*16;
    for (int i=tid;i<16*128;i+=128) Ys[i>>7][i&127] = g_yraw[(size_t)(m0 + (i>>7))*128 + (i&127)];
    __syncthreads();
    int col = (tid & 15)*4;
    int r0  = (tid >> 4)*2;
    float a0c[4]={0,0,0,0}, a1c[4]={0,0,0,0};
#pragma unroll 4
    for (int k=0;k<128;k++){
        float a0 = Ys[r0][k], a1 = Ys[r0+1][k];
        float4 w = *(const float4*)&Ws[k][col];
        a0c[0]+=a0*w.x; a0c[1]+=a0*w.y; a0c[2]+=a0*w.z; a0c[3]+=a0*w.w;
        a1c[0]+=a1*w.x; a1c[1]+=a1*w.y; a1c[2]+=a1*w.z; a1c[3]+=a1*w.w;
    }
#pragma unroll
    for (int rr=0;rr<2;rr++){
        int m = m0 + r0 + rr;
        int hh = m & 15;
        float dv = Dp[hh];
        float* accp = rr ? a1c : a0c;
#pragma unroll
        for (int j2=0;j2<4;j2++){
            int o = m*64 + col + j2;
            float v = accp[j2] + dv * g_xsilu[o];
            g_y3[o] = v * g_zsilu[o];
        }
    }
}

// ---------------- launch ----------------
extern "C" void kernel_launch(void* const* d_in, const int* in_sizes, int n_in,
                              void* d_out, int out_size)
{
    const float* u        = (const float*)d_in[0];
    const float* W_in     = (const float*)d_in[1];
    const float* b_in     = (const float*)d_in[2];
    const float* W_xup    = (const float*)d_in[3];
    const float* W_ydown  = (const float*)d_in[4];
    const float* A_log    = (const float*)d_in[5];
    const float* theta_log= (const float*)d_in[6];
    const float* D_param  = (const float*)d_in[7];
    const float* wB       = (const float*)d_in[8];
    const float* wC       = (const float*)d_in[9];
    const float* bias_B   = (const float*)d_in[10];
    const float* bias_C   = (const float*)d_in[11];
    const float* W_out    = (const float*)d_in[12];
    float* out = (float*)d_out;

    float *p_proj, *p_y3;
    cudaGetSymbolAddress((void**)&p_proj, g_proj);
    cudaGetSymbolAddress((void**)&p_y3,   g_y3);

    // 1. proj = u @ W_in + b_in   [2048 x 2568, K=512]   bf16-split HMMA
    {
        dim3 grid((DPROJ + 127)/128, LSEQ/128);
        k_gemm_bf16s<128><<<grid, 256>>>(LSEQ, DPROJ, DMODEL, u, W_in, b_in, p_proj);
    }
    // 2. gates / rmsnorm / dt
    k_post<<<LSEQ, 256>>>(wB, wC, bias_B, bias_C, A_log);
    // 3. dt cumsum + chunk decays
    k_scan_dt<<<1, 128>>>(A_log);
    // 4. RoPE
    k_rope<<<(LSEQ*GN*16 + 255)/256, 256>>>(theta_log);
    // 5. x_up
    k_xup<<<(LSEQ*HH)/16, 256>>>(W_xup);
    // 6-8. chunked recurrence
    k_passA<<<dim3(16, HH, NC), 128>>>();
    k_passB<<<128, 256>>>();
    k_passC<<<dim3(16, HH, NC), 128>>>();
    // 9. ydown + skip + gate
    k_ydown<<<(LSEQ*HH)/16, 128>>>(W_ydown, D_param);
    // 10. out = y3 @ W_out   [2048 x 512, K=1024]   bf16-split HMMA, BN=64 for occupancy
    {
        dim3 grid(DMODEL/64, LSEQ/128);
        k_gemm_bf16s<64><<<grid, 256>>>(LSEQ, DMODEL, 1024, p_y3, W_out, nullptr, out);
    }
}

// round 11
// speedup vs baseline: 2.6142x; 1.0561x over previous
#include <cuda_runtime.h>
#include <cuda_bf16.h>
#include <cstdint>

// ---------------- problem dims ----------------
#define LSEQ 2048
#define DMODEL 512
#define DPROJ 2568
#define GN 4          // groups
#define NS 32         // d_state
#define HH 16         // heads
#define PP 64         // head dim
#define NC 16         // chunks
#define CH 128        // chunk len
#define EPSV 1e-5f

// proj row offsets: z[0,1024) x[1024,2048) B[2048,2304) C[2304,2560) dt[2560,2564) lam[2564,2568)

// ---------------- scratch (device globals; no allocs allowed) ----------------
__device__ float  g_proj [LSEQ*DPROJ];
__device__ float  g_zsilu[LSEQ*1024];
__device__ float  g_xsilu[LSEQ*1024];
__device__ float  g_Bm   [LSEQ*GN*64];
__device__ float  g_Cm   [LSEQ*GN*64];
__device__ float4 g_scal [LSEQ*GN];           // (dt, lam, decay, 0)
__device__ float  g_sdt  [LSEQ*GN];
__device__ float  g_Dc   [NC*GN];
__device__ float  g_xup  [LSEQ*HH*128];
__device__ float  g_F    [NC*HH*PP*NS];
__device__ float  g_S    [NC*HH*PP*NS];
__device__ float  g_yraw [LSEQ*HH*128];
__device__ float  g_y3   [LSEQ*1024];

// ---------------- bf16-split helpers ----------------
__device__ __forceinline__ void split2(float x, float y, unsigned int& h, unsigned int& l){
    __nv_bfloat162 H = __floats2bfloat162_rn(x, y);
    float rx = x - __bfloat162float(H.x);
    float ry = y - __bfloat162float(H.y);
    __nv_bfloat162 L = __floats2bfloat162_rn(rx, ry);
    h = *reinterpret_cast<unsigned int*>(&H);
    l = *reinterpret_cast<unsigned int*>(&L);
}

__device__ __forceinline__ void mma_bf16(float* d, const unsigned int* a, const unsigned int* b){
    asm volatile("mma.sync.aligned.m16n8k16.row.col.f32.bf16.bf16.f32 "
        "{%0,%1,%2,%3}, {%4,%5,%6,%7}, {%8,%9}, {%0,%1,%2,%3};"
        : "+f"(d[0]),"+f"(d[1]),"+f"(d[2]),"+f"(d[3])
        : "r"(a[0]),"r"(a[1]),"r"(a[2]),"r"(a[3]), "r"(b[0]),"r"(b[1]));
}

// ---------------- tensor-core GEMM: C = A[MxK]@B[KxN] (+bias), 3x bf16 split ----------------
// block 128 x BN, BK=16, 8 warps (4 m x 2 n), DOUBLE-BUFFERED smem.
template<int BN>
__global__ __launch_bounds__(256) void k_gemm_bf16s(
    int M, int N, int K,
    const float* __restrict__ A,
    const float* __restrict__ B,
    const float* __restrict__ bias,
    float* __restrict__ C)
{
    const int BM=128;
    const int JW  = BN/16;     // n-subtiles per warp
    const int NB4 = BN/4;      // B staging col4 groups
    const int NBITEMS = 8*NB4;

    __shared__ unsigned int Ah[2][8][BM+8];
    __shared__ unsigned int Al[2][8][BM+8];
    __shared__ unsigned int Bh[2][8][BN+8];
    __shared__ unsigned int Bl[2][8][BN+8];

    const int tid  = threadIdx.x;
    const int lane = tid & 31;
    const int warp = tid >> 5;
    const int warpM = warp >> 1;
    const int warpN = warp & 1;
    const int rowBase = blockIdx.y * BM;
    const int colBase = blockIdx.x * BN;
    const int kq = lane & 3;

    float acc[2][JW][4];
#pragma unroll
    for (int t=0;t<2;t++)
#pragma unroll
        for (int j=0;j<JW;j++)
#pragma unroll
            for (int q=0;q<4;q++) acc[t][j][q]=0.f;

    const int ar0 = tid >> 2;          // 0..63
    const int ac0 = (tid & 3) * 4;     // 0,4,8,12
    const int br2 = tid / NB4;
    const int bcc = (tid % NB4) * 4;
    const bool bact = (tid < NBITEMS);

    float4 pa0, pa1, pb0, pb1;

#define LOADT(kk0) { \
    pa0 = *(const float4*)&A[(size_t)(rowBase+ar0   )*K + (kk0) + ac0]; \
    pa1 = *(const float4*)&A[(size_t)(rowBase+ar0+64)*K + (kk0) + ac0]; \
    if (bact){ int gc = colBase + bcc; \
        if (gc < N){ \
            pb0 = *(const float4*)&B[(size_t)((kk0)+2*br2  )*N + gc]; \
            pb1 = *(const float4*)&B[(size_t)((kk0)+2*br2+1)*N + gc]; \
        } else { pb0 = make_float4(0,0,0,0); pb1 = pb0; } } }

#define STORET(bb) { \
    split2(pa0.x, pa0.y, Ah[bb][ac0/2  ][ar0   ], Al[bb][ac0/2  ][ar0   ]); \
    split2(pa0.z, pa0.w, Ah[bb][ac0/2+1][ar0   ], Al[bb][ac0/2+1][ar0   ]); \
    split2(pa1.x, pa1.y, Ah[bb][ac0/2  ][ar0+64], Al[bb][ac0/2  ][ar0+64]); \
    split2(pa1.z, pa1.w, Ah[bb][ac0/2+1][ar0+64], Al[bb][ac0/2+1][ar0+64]); \
    if (bact){ \
        split2(pb0.x, pb1.x, Bh[bb][br2][bcc+0], Bl[bb][br2][bcc+0]); \
        split2(pb0.y, pb1.y, Bh[bb][br2][bcc+1], Bl[bb][br2][bcc+1]); \
        split2(pb0.z, pb1.z, Bh[bb][br2][bcc+2], Bl[bb][br2][bcc+2]); \
        split2(pb0.w, pb1.w, Bh[bb][br2][bcc+3], Bl[bb][br2][bcc+3]); } }

    LOADT(0);
    STORET(0);
    __syncthreads();

    int cur = 0;
    for (int k0=0; k0<K; k0+=16){
        const bool more = (k0+16 < K);
        if (more){ LOADT(k0+16); }

        // fragment loads from current buffer
        unsigned int ah[2][4], alr[2][4];
#pragma unroll
        for (int t=0;t<2;t++){
            int r = warpM*32 + t*16 + (lane>>2);
            ah[t][0]=Ah[cur][kq  ][r];   alr[t][0]=Al[cur][kq  ][r];
            ah[t][1]=Ah[cur][kq  ][r+8]; alr[t][1]=Al[cur][kq  ][r+8];
            ah[t][2]=Ah[cur][kq+4][r];   alr[t][2]=Al[cur][kq+4][r];
            ah[t][3]=Ah[cur][kq+4][r+8]; alr[t][3]=Al[cur][kq+4][r+8];
        }
        unsigned int bh[JW][2], blr[JW][2];
#pragma unroll
        for (int j=0;j<JW;j++){
            int cb = warpN*(BN/2) + j*8 + (lane>>2);
            bh[j][0]=Bh[cur][kq  ][cb];  blr[j][0]=Bl[cur][kq  ][cb];
            bh[j][1]=Bh[cur][kq+4][cb];  blr[j][1]=Bl[cur][kq+4][cb];
        }
        // MMAs overlap with outstanding LDGs
#pragma unroll
        for (int t=0;t<2;t++)
#pragma unroll
            for (int j=0;j<JW;j++){
                mma_bf16(acc[t][j], ah[t],  bh[j]);
                mma_bf16(acc[t][j], ah[t],  blr[j]);
                mma_bf16(acc[t][j], alr[t], bh[j]);
            }
        if (more){ STORET(cur^1); }
        __syncthreads();
        cur ^= 1;
    }

    // epilogue
#pragma unroll
    for (int t=0;t<2;t++){
#pragma unroll
        for (int j=0;j<JW;j++){
            int row = rowBase + warpM*32 + t*16 + (lane>>2);
            int col = colBase + warpN*(BN/2) + j*8 + 2*(lane&3);
            if (col < N){
                float b0 = bias ? bias[col] : 0.f;
                float b1 = (bias && col+1<N) ? bias[col+1] : 0.f;
                C[(size_t)row*N + col] = acc[t][j][0] + b0;
                if (col+1 < N) C[(size_t)row*N + col+1] = acc[t][j][1] + b1;
                C[(size_t)(row+8)*N + col] = acc[t][j][2] + b0;
                if (col+1 < N) C[(size_t)(row+8)*N + col+1] = acc[t][j][3] + b1;
            }
        }
    }
#undef LOADT
#undef STORET
}

// ---------------- postprocess: gates, RMSNorm B/C, dt/lam/decay ----------------
__global__ void k_post(const float* __restrict__ wB, const float* __restrict__ wC,
                       const float* __restrict__ biasB, const float* __restrict__ biasC,
                       const float* __restrict__ A_log)
{
    const int l = blockIdx.x;
    const int tid = threadIdx.x;         // 256 threads
    const float* row = g_proj + (size_t)l*DPROJ;

    for (int i=tid;i<1024;i+=256){
        float v = row[i];
        g_zsilu[l*1024+i] = v / (1.f + expf(-v));
        float w = row[1024+i];
        g_xsilu[l*1024+i] = w / (1.f + expf(-w));
    }

    __shared__ float pB[8], pC[8];
    float vB = row[2048+tid];
    float vC = row[2304+tid];
    float sB = vB*vB, sC = vC*vC;
#pragma unroll
    for (int o=16;o>0;o>>=1){
        sB += __shfl_xor_sync(0xffffffffu, sB, o);
        sC += __shfl_xor_sync(0xffffffffu, sC, o);
    }
    int wp = tid >> 5;
    if ((tid & 31) == 0){ pB[wp]=sB; pC[wp]=sC; }
    __syncthreads();

    int g = tid >> 6, j = tid & 63;
    float mB = (pB[2*g]+pB[2*g+1]) * (1.f/64.f);
    float mC = (pC[2*g]+pC[2*g+1]) * (1.f/64.f);
    g_Bm[l*256+tid] = vB * rsqrtf(mB + EPSV) * wB[j] + biasB[tid];
    g_Cm[l*256+tid] = vC * rsqrtf(mC + EPSV) * wC[j] + biasC[tid];

    if (tid < GN){
        float dtr = row[2560+tid];
        float dt  = (dtr > 20.f) ? dtr : log1pf(expf(dtr));
        float lam = 1.f/(1.f+expf(-row[2564+tid]));
        float A   = -expf(A_log[tid]);
        g_scal[l*GN+tid] = make_float4(dt, lam, expf(dt*A), 0.f);
    }
}

// ---------------- dt cumsum (4 sequences of 2048) + per-chunk decays ----------------
__global__ void k_scan_dt(const float* __restrict__ A_log)
{
    int g = threadIdx.x >> 5;
    int lane = threadIdx.x & 31;
    float carry = 0.f;
    for (int b=0;b<64;b++){
        int l = b*32 + lane;
        float v = g_scal[l*GN+g].x;
#pragma unroll
        for (int o=1;o<32;o<<=1){
            float t = __shfl_up_sync(0xffffffffu, v, o);
            if (lane >= o) v += t;
        }
        g_sdt[l*GN+g] = carry + v;
        carry += __shfl_sync(0xffffffffu, v, 31);
    }
    __syncthreads();
    int t = threadIdx.x;
    if (t < NC*GN){
        int c = t >> 2, gg = t & 3;
        float A = -expf(A_log[gg]);
        float e = g_sdt[(c*CH + CH-1)*GN + gg];
        float s = c ? g_sdt[(c*CH - 1)*GN + gg] : 0.f;
        g_Dc[t] = expf(A*(e-s));
    }
}

// ---------------- RoPE applied in-place to Bm, Cm ----------------
__global__ void k_rope(const float* __restrict__ theta_log)
{
    int idx = blockIdx.x*256 + threadIdx.x;
    if (idx >= LSEQ*GN*16) return;
    int j = idx & 15;
    int g = (idx >> 4) & 3;
    int l = idx >> 6;
    float th = expf(theta_log[g*16+j]);
    float ang = g_sdt[l*GN+g] * th;
    float cs = cosf(ang), sn = sinf(ang);
    int base = l*256 + g*64 + j*4;
#pragma unroll
    for (int r=0;r<2;r++){
        float re = g_Bm[base+r],   im = g_Bm[base+2+r];
        g_Bm[base+r]   = re*cs - im*sn;
        g_Bm[base+2+r] = re*sn + im*cs;
        float re2 = g_Cm[base+r],  im2 = g_Cm[base+2+r];
        g_Cm[base+r]   = re2*cs - im2*sn;
        g_Cm[base+2+r] = re2*sn + im2*cs;
    }
}

// ---------------- x_up = xsilu[L*H,64] @ W_xup[64,128] ----------------
__global__ void k_xup(const float* __restrict__ Wx)
{
    __shared__ float Ws[64][128];
    __shared__ float Xs[16][64];
    int tid = threadIdx.x;  // 256
    for (int i=tid;i<64*128;i+=256) Ws[i>>7][i&127] = Wx[i];
    int m0 = blockIdx.x*16;
    for (int i=tid;i<16*64;i+=256)  Xs[i>>6][i&63]  = g_xsilu[(m0 + (i>>6))*64 + (i&63)];
    __syncthreads();
    int col = (tid & 31)*4;
    int r0  = (tid >> 5)*2;
    float a0c[4]={0,0,0,0}, a1c[4]={0,0,0,0};
#pragma unroll 4
    for (int k=0;k<64;k++){
        float a0 = Xs[r0][k], a1 = Xs[r0+1][k];
        float4 w = *(const float4*)&Ws[k][col];
        a0c[0]+=a0*w.x; a0c[1]+=a0*w.y; a0c[2]+=a0*w.z; a0c[3]+=a0*w.w;
        a1c[0]+=a1*w.x; a1c[1]+=a1*w.y; a1c[2]+=a1*w.z; a1c[3]+=a1*w.w;
    }
#pragma unroll
    for (int j2=0;j2<4;j2++){
        g_xup[(size_t)(m0+r0  )*128 + col + j2] = a0c[j2];
        g_xup[(size_t)(m0+r0+1)*128 + col + j2] = a1c[j2];
    }
}

// ---------------- pass A: chunk-local scan, emit final states ----------------
__global__ void k_passA()
{
    const int c = blockIdx.z, h = blockIdx.y;
    const int p = blockIdx.x*4 + (threadIdx.x >> 5);
    const int n = threadIdx.x & 31;
    const int g = h >> 2;
    const int t0 = c*CH;

    float u_prev = 0.f;
    if (c){
        int t = t0-1;
        float2 B = *(const float2*)&g_Bm[(t*GN+g)*64 + n*2];
        float2 X = *(const float2*)&g_xup[(size_t)(t*HH+h)*128 + p*2];
        float4 s = g_scal[t*GN+g];
        u_prev = s.x*(B.x*X.x + B.y*X.y);
    }
    float hs = 0.f;
#pragma unroll 4
    for (int t=t0; t<t0+CH; t++){
        float2 B = *(const float2*)&g_Bm[(t*GN+g)*64 + n*2];
        float2 X = *(const float2*)&g_xup[(size_t)(t*HH+h)*128 + p*2];
        float4 s = g_scal[t*GN+g];
        float uss = s.x*(B.x*X.x + B.y*X.y);
        float ut  = s.y*uss + (1.f-s.y)*u_prev;
        u_prev = uss;
        hs = hs*s.z + ut;
    }
    g_F[((c*HH+h)*PP+p)*NS + n] = hs;
}

// ---------------- pass B: inter-chunk combine (16-step scan) ----------------
__global__ void k_passB()
{
    int gw = blockIdx.x*8 + (threadIdx.x >> 5);   // 1024 warps total
    int n  = threadIdx.x & 31;
    int h = gw >> 6, p = gw & 63;
    int g = h >> 2;
    float S = 0.f;
#pragma unroll
    for (int c=0;c<NC;c++){
        int idx = ((c*HH+h)*PP+p)*NS + n;
        g_S[idx] = S;
        S = S*g_Dc[c*GN+g] + g_F[idx];
    }
}

// ---------------- pass C: rescan with incoming state, produce y_raw ----------------
__global__ void k_passC()
{
    const int c = blockIdx.z, h = blockIdx.y;
    const int p = blockIdx.x*4 + (threadIdx.x >> 5);
    const int n = threadIdx.x & 31;
    const int g = h >> 2;
    const int t0 = c*CH;

    float u_prev = 0.f;
    if (c){
        int t = t0-1;
        float2 B = *(const float2*)&g_Bm[(t*GN+g)*64 + n*2];
        float2 X = *(const float2*)&g_xup[(size_t)(t*HH+h)*128 + p*2];
        float4 s = g_scal[t*GN+g];
        u_prev = s.x*(B.x*X.x + B.y*X.y);
    }
    float hs = g_S[((c*HH+h)*PP+p)*NS + n];
    const bool isLane0  = (n == 0);
    const bool isLane16 = (n == 16);
    const bool low = (n < 16);
#pragma unroll 2
    for (int t=t0; t<t0+CH; t++){
        float2 B = *(const float2*)&g_Bm[(t*GN+g)*64 + n*2];
        float2 X = *(const float2*)&g_xup[(size_t)(t*HH+h)*128 + p*2];
        float4 s = g_scal[t*GN+g];
        float uss = s.x*(B.x*X.x + B.y*X.y);
        float ut  = s.y*uss + (1.f-s.y)*u_prev;
        u_prev = uss;
        hs = hs*s.z + ut;

        float2 Cv = *(const float2*)&g_Cm[(t*GN+g)*64 + n*2];
        float y0 = hs*Cv.x, y1 = hs*Cv.y;
        // split reduction: lanes 0-15 reduce y0, lanes 16-31 reduce y1 (6 shfl)
        float t0s = __shfl_xor_sync(0xffffffffu, y0, 16);
        float t1s = __shfl_xor_sync(0xffffffffu, y1, 16);
        float v = low ? (y0 + t0s) : (y1 + t1s);
#pragma unroll
        for (int o=8;o>0;o>>=1) v += __shfl_xor_sync(0xffffffffu, v, o);
        float* dst = &g_yraw[(size_t)(t*HH+h)*128 + p*2];
        if (isLane0)  dst[0] = v;
        if (isLane16) dst[1] = v;
    }
}

// ---------------- ydown + skip + z-gate ----------------
__global__ void k_ydown(const float* __restrict__ Wy, const float* __restrict__ Dp)
{
    __shared__ float Ws[128][64];
    __shared__ float Ys[16][128];
    int tid = threadIdx.x;  // 128
    for (int i=tid;i<128*64;i+=128) Ws[i>>6][i&63]  = Wy[i];
    int m0 = blockIdx.x*16;
    for (int i=tid;i<16*128;i+=128) Ys[i>>7][i&127] = g_yraw[(size_t)(m0 + (i>>7))*128 + (i&127)];
    __syncthreads();
    int col = (tid & 15)*4;
    int r0  = (tid >> 4)*2;
    float a0c[4]={0,0,0,0}, a1c[4]={0,0,0,0};
#pragma unroll 4
    for (int k=0;k<128;k++){
        float a0 = Ys[r0][k], a1 = Ys[r0+1][k];
        float4 w = *(const float4*)&Ws[k][col];
        a0c[0]+=a0*w.x; a0c[1]+=a0*w.y; a0c[2]+=a0*w.z; a0c[3]+=a0*w.w;
        a1c[0]+=a1*w.x; a1c[1]+=a1*w.y; a1c[2]+=a1*w.z; a1c[3]+=a1*w.w;
    }
#pragma unroll
    for (int rr=0;rr<2;rr++){
        int m = m0 + r0 + rr;
        int hh = m & 15;
        float dv = Dp[hh];
        float* accp = rr ? a1c : a0c;
#pragma unroll
        for (int j2=0;j2<4;j2++){
            int o = m*64 + col + j2;
            float v = accp[j2] + dv * g_xsilu[o];
            g_y3[o] = v * g_zsilu[o];
        }
    }
}

// ---------------- launch ----------------
extern "C" void kernel_launch(void* const* d_in, const int* in_sizes, int n_in,
                              void* d_out, int out_size)
{
    const float* u        = (const float*)d_in[0];
    const float* W_in     = (const float*)d_in[1];
    const float* b_in     = (const float*)d_in[2];
    const float* W_xup    = (const float*)d_in[3];
    const float* W_ydown  = (const float*)d_in[4];
    const float* A_log    = (const float*)d_in[5];
    const float* theta_log= (const float*)d_in[6];
    const float* D_param  = (const float*)d_in[7];
    const float* wB       = (const float*)d_in[8];
    const float* wC       = (const float*)d_in[9];
    const float* bias_B   = (const float*)d_in[10];
    const float* bias_C   = (const float*)d_in[11];
    const float* W_out    = (const float*)d_in[12];
    float* out = (float*)d_out;

    float *p_proj, *p_y3;
    cudaGetSymbolAddress((void**)&p_proj, g_proj);
    cudaGetSymbolAddress((void**)&p_y3,   g_y3);

    // 1. proj = u @ W_in + b_in   [2048 x 2568, K=512]   bf16-split HMMA, double-buffered
    {
        dim3 grid((DPROJ + 127)/128, LSEQ/128);
        k_gemm_bf16s<128><<<grid, 256>>>(LSEQ, DPROJ, DMODEL, u, W_in, b_in, p_proj);
    }
    // 2. gates / rmsnorm / dt
    k_post<<<LSEQ, 256>>>(wB, wC, bias_B, bias_C, A_log);
    // 3. dt cumsum + chunk decays
    k_scan_dt<<<1, 128>>>(A_log);
    // 4. RoPE
    k_rope<<<(LSEQ*GN*16 + 255)/256, 256>>>(theta_log);
    // 5. x_up
    k_xup<<<(LSEQ*HH)/16, 256>>>(W_xup);
    // 6-8. chunked recurrence
    k_passA<<<dim3(16, HH, NC), 128>>>();
    k_passB<<<128, 256>>>();
    k_passC<<<dim3(16, HH, NC), 128>>>();
    // 9. ydown + skip + gate
    k_ydown<<<(LSEQ*HH)/16, 128>>>(W_ydown, D_param);
    // 10. out = y3 @ W_out   [2048 x 512, K=1024]   bf16-split HMMA, BN=64 for occupancy
    {
        dim3 grid(DMODEL/64, LSEQ/128);
        k_gemm_bf16s<64><<<grid, 256>>>(LSEQ, DMODEL, 1024, p_y3, W_out, nullptr, out);
    }
}

// round 12
// speedup vs baseline: 2.7339x; 1.0458x over previous
#include <cuda_runtime.h>
#include <cuda_bf16.h>
#include <cstdint>

// ---------------- problem dims ----------------
#define LSEQ 2048
#define DMODEL 512
#define DPROJ 2568
#define GN 4          // groups
#define NS 32         // d_state
#define HH 16         // heads
#define PP 64         // head dim
#define NC 16         // chunks
#define CH 128        // chunk len
#define EPSV 1e-5f

// proj row offsets: z[0,1024) x[1024,2048) B[2048,2304) C[2304,2560) dt[2560,2564) lam[2564,2568)

// ---------------- scratch (device globals; no allocs allowed) ----------------
__device__ float  g_proj [LSEQ*DPROJ];
__device__ float  g_zsilu[LSEQ*1024];
__device__ float  g_xsilu[LSEQ*1024];
__device__ float  g_Bm   [LSEQ*GN*64];
__device__ float  g_Cm   [LSEQ*GN*64];
__device__ float4 g_scal [LSEQ*GN];           // (dt, lam, decay, 0)
__device__ float  g_sdt  [LSEQ*GN];
__device__ float  g_Dc   [NC*GN];
__device__ float  g_xup  [LSEQ*HH*128];
__device__ float  g_F    [NC*HH*PP*NS];
__device__ float  g_S    [NC*HH*PP*NS];
__device__ float  g_yraw [LSEQ*HH*128];
__device__ float  g_y3   [LSEQ*1024];

// ---------------- bf16-split helpers ----------------
__device__ __forceinline__ void split2(float x, float y, unsigned int& h, unsigned int& l){
    __nv_bfloat162 H = __floats2bfloat162_rn(x, y);
    float rx = x - __bfloat162float(H.x);
    float ry = y - __bfloat162float(H.y);
    __nv_bfloat162 L = __floats2bfloat162_rn(rx, ry);
    h = *reinterpret_cast<unsigned int*>(&H);
    l = *reinterpret_cast<unsigned int*>(&L);
}

__device__ __forceinline__ void mma_bf16(float* d, const unsigned int* a, const unsigned int* b){
    asm volatile("mma.sync.aligned.m16n8k16.row.col.f32.bf16.bf16.f32 "
        "{%0,%1,%2,%3}, {%4,%5,%6,%7}, {%8,%9}, {%0,%1,%2,%3};"
        : "+f"(d[0]),"+f"(d[1]),"+f"(d[2]),"+f"(d[3])
        : "r"(a[0]),"r"(a[1]),"r"(a[2]),"r"(a[3]), "r"(b[0]),"r"(b[1]));
}

// ---------------- tensor-core GEMM: C = A[MxK]@B[KxN] (+bias), 3x bf16 split ----------------
// block 128 x BN, BK=16, 8 warps as 2m x 4n (warp tile 64 x BN/4), double-buffered.
// Targets 2 CTAs/SM (<=128 regs).
template<int BN>
__global__ __launch_bounds__(256, 2) void k_gemm_bf16s(
    int M, int N, int K,
    const float* __restrict__ A,
    const float* __restrict__ B,
    const float* __restrict__ bias,
    float* __restrict__ C)
{
    const int BM=128;
    const int WN  = BN/4;      // warp n extent
    const int JW  = WN/8;      // n-subtiles (8 cols) per warp
    const int NB4 = BN/4;      // B staging col4 groups
    const int NBITEMS = 8*NB4;

    __shared__ unsigned int Ah[2][8][BM+8];
    __shared__ unsigned int Al[2][8][BM+8];
    __shared__ unsigned int Bh[2][8][BN+8];
    __shared__ unsigned int Bl[2][8][BN+8];

    const int tid  = threadIdx.x;
    const int lane = tid & 31;
    const int warp = tid >> 5;
    const int warpM = warp >> 2;       // 0..1 -> 64 rows each
    const int warpN = warp & 3;        // 0..3 -> WN cols each
    const int rowBase = blockIdx.y * BM;
    const int colBase = blockIdx.x * BN;
    const int kq = lane & 3;

    float acc[4][JW][4];
#pragma unroll
    for (int t=0;t<4;t++)
#pragma unroll
        for (int j=0;j<JW;j++)
#pragma unroll
            for (int q=0;q<4;q++) acc[t][j][q]=0.f;

    const int ar0 = tid >> 2;          // 0..63
    const int ac0 = (tid & 3) * 4;     // 0,4,8,12
    const int br2 = tid / NB4;
    const int bcc = (tid % NB4) * 4;
    const bool bact = (tid < NBITEMS);

    float4 pa0, pa1, pb0, pb1;

#define LOADT(kk0) { \
    pa0 = *(const float4*)&A[(size_t)(rowBase+ar0   )*K + (kk0) + ac0]; \
    pa1 = *(const float4*)&A[(size_t)(rowBase+ar0+64)*K + (kk0) + ac0]; \
    if (bact){ int gc = colBase + bcc; \
        if (gc < N){ \
            pb0 = *(const float4*)&B[(size_t)((kk0)+2*br2  )*N + gc]; \
            pb1 = *(const float4*)&B[(size_t)((kk0)+2*br2+1)*N + gc]; \
        } else { pb0 = make_float4(0,0,0,0); pb1 = pb0; } } }

#define STORET(bb) { \
    split2(pa0.x, pa0.y, Ah[bb][ac0/2  ][ar0   ], Al[bb][ac0/2  ][ar0   ]); \
    split2(pa0.z, pa0.w, Ah[bb][ac0/2+1][ar0   ], Al[bb][ac0/2+1][ar0   ]); \
    split2(pa1.x, pa1.y, Ah[bb][ac0/2  ][ar0+64], Al[bb][ac0/2  ][ar0+64]); \
    split2(pa1.z, pa1.w, Ah[bb][ac0/2+1][ar0+64], Al[bb][ac0/2+1][ar0+64]); \
    if (bact){ \
        split2(pb0.x, pb1.x, Bh[bb][br2][bcc+0], Bl[bb][br2][bcc+0]); \
        split2(pb0.y, pb1.y, Bh[bb][br2][bcc+1], Bl[bb][br2][bcc+1]); \
        split2(pb0.z, pb1.z, Bh[bb][br2][bcc+2], Bl[bb][br2][bcc+2]); \
        split2(pb0.w, pb1.w, Bh[bb][br2][bcc+3], Bl[bb][br2][bcc+3]); } }

    LOADT(0);
    STORET(0);
    __syncthreads();

    int cur = 0;
    for (int k0=0; k0<K; k0+=16){
        const bool more = (k0+16 < K);
        if (more){ LOADT(k0+16); }

        // A fragments: 4 m-subtiles of 16 rows
        unsigned int ah[4][4], alr[4][4];
#pragma unroll
        for (int t=0;t<4;t++){
            int r = warpM*64 + t*16 + (lane>>2);
            ah[t][0]=Ah[cur][kq  ][r];   alr[t][0]=Al[cur][kq  ][r];
            ah[t][1]=Ah[cur][kq  ][r+8]; alr[t][1]=Al[cur][kq  ][r+8];
            ah[t][2]=Ah[cur][kq+4][r];   alr[t][2]=Al[cur][kq+4][r];
            ah[t][3]=Ah[cur][kq+4][r+8]; alr[t][3]=Al[cur][kq+4][r+8];
        }
        unsigned int bh[JW][2], blr[JW][2];
#pragma unroll
        for (int j=0;j<JW;j++){
            int cb = warpN*WN + j*8 + (lane>>2);
            bh[j][0]=Bh[cur][kq  ][cb];  blr[j][0]=Bl[cur][kq  ][cb];
            bh[j][1]=Bh[cur][kq+4][cb];  blr[j][1]=Bl[cur][kq+4][cb];
        }
#pragma unroll
        for (int t=0;t<4;t++)
#pragma unroll
            for (int j=0;j<JW;j++){
                mma_bf16(acc[t][j], ah[t],  bh[j]);
                mma_bf16(acc[t][j], ah[t],  blr[j]);
                mma_bf16(acc[t][j], alr[t], bh[j]);
            }
        if (more){ STORET(cur^1); }
        __syncthreads();
        cur ^= 1;
    }

    // epilogue
#pragma unroll
    for (int t=0;t<4;t++){
#pragma unroll
        for (int j=0;j<JW;j++){
            int row = rowBase + warpM*64 + t*16 + (lane>>2);
            int col = colBase + warpN*WN + j*8 + 2*(lane&3);
            if (col < N){
                float b0 = bias ? bias[col] : 0.f;
                float b1 = (bias && col+1<N) ? bias[col+1] : 0.f;
                C[(size_t)row*N + col] = acc[t][j][0] + b0;
                if (col+1 < N) C[(size_t)row*N + col+1] = acc[t][j][1] + b1;
                C[(size_t)(row+8)*N + col] = acc[t][j][2] + b0;
                if (col+1 < N) C[(size_t)(row+8)*N + col+1] = acc[t][j][3] + b1;
            }
        }
    }
#undef LOADT
#undef STORET
}

// ---------------- postprocess: gates, RMSNorm B/C, dt/lam/decay ----------------
__global__ void k_post(const float* __restrict__ wB, const float* __restrict__ wC,
                       const float* __restrict__ biasB, const float* __restrict__ biasC,
                       const float* __restrict__ A_log)
{
    const int l = blockIdx.x;
    const int tid = threadIdx.x;         // 256 threads
    const float* row = g_proj + (size_t)l*DPROJ;

    for (int i=tid;i<1024;i+=256){
        float v = row[i];
        g_zsilu[l*1024+i] = v / (1.f + expf(-v));
        float w = row[1024+i];
        g_xsilu[l*1024+i] = w / (1.f + expf(-w));
    }

    __shared__ float pB[8], pC[8];
    float vB = row[2048+tid];
    float vC = row[2304+tid];
    float sB = vB*vB, sC = vC*vC;
#pragma unroll
    for (int o=16;o>0;o>>=1){
        sB += __shfl_xor_sync(0xffffffffu, sB, o);
        sC += __shfl_xor_sync(0xffffffffu, sC, o);
    }
    int wp = tid >> 5;
    if ((tid & 31) == 0){ pB[wp]=sB; pC[wp]=sC; }
    __syncthreads();

    int g = tid >> 6, j = tid & 63;
    float mB = (pB[2*g]+pB[2*g+1]) * (1.f/64.f);
    float mC = (pC[2*g]+pC[2*g+1]) * (1.f/64.f);
    g_Bm[l*256+tid] = vB * rsqrtf(mB + EPSV) * wB[j] + biasB[tid];
    g_Cm[l*256+tid] = vC * rsqrtf(mC + EPSV) * wC[j] + biasC[tid];

    if (tid < GN){
        float dtr = row[2560+tid];
        float dt  = (dtr > 20.f) ? dtr : log1pf(expf(dtr));
        float lam = 1.f/(1.f+expf(-row[2564+tid]));
        float A   = -expf(A_log[tid]);
        g_scal[l*GN+tid] = make_float4(dt, lam, expf(dt*A), 0.f);
    }
}

// ---------------- dt cumsum (4 sequences of 2048) + per-chunk decays ----------------
__global__ void k_scan_dt(const float* __restrict__ A_log)
{
    int g = threadIdx.x >> 5;
    int lane = threadIdx.x & 31;
    float carry = 0.f;
    for (int b=0;b<64;b++){
        int l = b*32 + lane;
        float v = g_scal[l*GN+g].x;
#pragma unroll
        for (int o=1;o<32;o<<=1){
            float t = __shfl_up_sync(0xffffffffu, v, o);
            if (lane >= o) v += t;
        }
        g_sdt[l*GN+g] = carry + v;
        carry += __shfl_sync(0xffffffffu, v, 31);
    }
    __syncthreads();
    int t = threadIdx.x;
    if (t < NC*GN){
        int c = t >> 2, gg = t & 3;
        float A = -expf(A_log[gg]);
        float e = g_sdt[(c*CH + CH-1)*GN + gg];
        float s = c ? g_sdt[(c*CH - 1)*GN + gg] : 0.f;
        g_Dc[t] = expf(A*(e-s));
    }
}

// ---------------- RoPE applied in-place to Bm, Cm ----------------
__global__ void k_rope(const float* __restrict__ theta_log)
{
    int idx = blockIdx.x*256 + threadIdx.x;
    if (idx >= LSEQ*GN*16) return;
    int j = idx & 15;
    int g = (idx >> 4) & 3;
    int l = idx >> 6;
    float th = expf(theta_log[g*16+j]);
    float ang = g_sdt[l*GN+g] * th;
    float cs = cosf(ang), sn = sinf(ang);
    int base = l*256 + g*64 + j*4;
#pragma unroll
    for (int r=0;r<2;r++){
        float re = g_Bm[base+r],   im = g_Bm[base+2+r];
        g_Bm[base+r]   = re*cs - im*sn;
        g_Bm[base+2+r] = re*sn + im*cs;
        float re2 = g_Cm[base+r],  im2 = g_Cm[base+2+r];
        g_Cm[base+r]   = re2*cs - im2*sn;
        g_Cm[base+2+r] = re2*sn + im2*cs;
    }
}

// ---------------- x_up = xsilu[L*H,64] @ W_xup[64,128] ----------------
__global__ void k_xup(const float* __restrict__ Wx)
{
    __shared__ float Ws[64][128];
    __shared__ float Xs[16][64];
    int tid = threadIdx.x;  // 256
    for (int i=tid;i<64*128;i+=256) Ws[i>>7][i&127] = Wx[i];
    int m0 = blockIdx.x*16;
    for (int i=tid;i<16*64;i+=256)  Xs[i>>6][i&63]  = g_xsilu[(m0 + (i>>6))*64 + (i&63)];
    __syncthreads();
    int col = (tid & 31)*4;
    int r0  = (tid >> 5)*2;
    float a0c[4]={0,0,0,0}, a1c[4]={0,0,0,0};
#pragma unroll 4
    for (int k=0;k<64;k++){
        float a0 = Xs[r0][k], a1 = Xs[r0+1][k];
        float4 w = *(const float4*)&Ws[k][col];
        a0c[0]+=a0*w.x; a0c[1]+=a0*w.y; a0c[2]+=a0*w.z; a0c[3]+=a0*w.w;
        a1c[0]+=a1*w.x; a1c[1]+=a1*w.y; a1c[2]+=a1*w.z; a1c[3]+=a1*w.w;
    }
#pragma unroll
    for (int j2=0;j2<4;j2++){
        g_xup[(size_t)(m0+r0  )*128 + col + j2] = a0c[j2];
        g_xup[(size_t)(m0+r0+1)*128 + col + j2] = a1c[j2];
    }
}

// ---------------- pass A: chunk-local scan, emit final states ----------------
__global__ void k_passA()
{
    const int c = blockIdx.z, h = blockIdx.y;
    const int p = blockIdx.x*4 + (threadIdx.x >> 5);
    const int n = threadIdx.x & 31;
    const int g = h >> 2;
    const int t0 = c*CH;

    float u_prev = 0.f;
    if (c){
        int t = t0-1;
        float2 B = *(const float2*)&g_Bm[(t*GN+g)*64 + n*2];
        float2 X = *(const float2*)&g_xup[(size_t)(t*HH+h)*128 + p*2];
        float4 s = g_scal[t*GN+g];
        u_prev = s.x*(B.x*X.x + B.y*X.y);
    }
    float hs = 0.f;
#pragma unroll 4
    for (int t=t0; t<t0+CH; t++){
        float2 B = *(const float2*)&g_Bm[(t*GN+g)*64 + n*2];
        float2 X = *(const float2*)&g_xup[(size_t)(t*HH+h)*128 + p*2];
        float4 s = g_scal[t*GN+g];
        float uss = s.x*(B.x*X.x + B.y*X.y);
        float ut  = s.y*uss + (1.f-s.y)*u_prev;
        u_prev = uss;
        hs = hs*s.z + ut;
    }
    g_F[((c*HH+h)*PP+p)*NS + n] = hs;
}

// ---------------- pass B: inter-chunk combine (16-step scan) ----------------
__global__ void k_passB()
{
    int gw = blockIdx.x*8 + (threadIdx.x >> 5);   // 1024 warps total
    int n  = threadIdx.x & 31;
    int h = gw >> 6, p = gw & 63;
    int g = h >> 2;
    float S = 0.f;
#pragma unroll
    for (int c=0;c<NC;c++){
        int idx = ((c*HH+h)*PP+p)*NS + n;
        g_S[idx] = S;
        S = S*g_Dc[c*GN+g] + g_F[idx];
    }
}

// ---------------- pass C: rescan with incoming state, produce y_raw ----------------
__global__ void k_passC()
{
    const int c = blockIdx.z, h = blockIdx.y;
    const int p = blockIdx.x*4 + (threadIdx.x >> 5);
    const int n = threadIdx.x & 31;
    const int g = h >> 2;
    const int t0 = c*CH;

    float u_prev = 0.f;
    if (c){
        int t = t0-1;
        float2 B = *(const float2*)&g_Bm[(t*GN+g)*64 + n*2];
        float2 X = *(const float2*)&g_xup[(size_t)(t*HH+h)*128 + p*2];
        float4 s = g_scal[t*GN+g];
        u_prev = s.x*(B.x*X.x + B.y*X.y);
    }
    float hs = g_S[((c*HH+h)*PP+p)*NS + n];
    const bool isLane0  = (n == 0);
    const bool isLane16 = (n == 16);
    const bool low = (n < 16);
#pragma unroll 2
    for (int t=t0; t<t0+CH; t++){
        float2 B = *(const float2*)&g_Bm[(t*GN+g)*64 + n*2];
        float2 X = *(const float2*)&g_xup[(size_t)(t*HH+h)*128 + p*2];
        float4 s = g_scal[t*GN+g];
        float uss = s.x*(B.x*X.x + B.y*X.y);
        float ut  = s.y*uss + (1.f-s.y)*u_prev;
        u_prev = uss;
        hs = hs*s.z + ut;

        float2 Cv = *(const float2*)&g_Cm[(t*GN+g)*64 + n*2];
        float y0 = hs*Cv.x, y1 = hs*Cv.y;
        float t0s = __shfl_xor_sync(0xffffffffu, y0, 16);
        float t1s = __shfl_xor_sync(0xffffffffu, y1, 16);
        float v = low ? (y0 + t0s) : (y1 + t1s);
#pragma unroll
        for (int o=8;o>0;o>>=1) v += __shfl_xor_sync(0xffffffffu, v, o);
        float* dst = &g_yraw[(size_t)(t*HH+h)*128 + p*2];
        if (isLane0)  dst[0] = v;
        if (isLane16) dst[1] = v;
    }
}

// ---------------- ydown + skip + z-gate ----------------
__global__ void k_ydown(const float* __restrict__ Wy, const float* __restrict__ Dp)
{
    __shared__ float Ws[128][64];
    __shared__ float Ys[16][128];
    int tid = threadIdx.x;  // 128
    for (int i=tid;i<128*64;i+=128) Ws[i>>6][i&63]  = Wy[i];
    int m0 = blockIdx.x*16;
    for (int i=tid;i<16*128;i+=128) Ys[i>>7][i&127] = g_yraw[(size_t)(m0 + (i>>7))*128 + (i&127)];
    __syncthreads();
    int col = (tid & 15)*4;
    int r0  = (tid >> 4)*2;
    float a0c[4]={0,0,0,0}, a1c[4]={0,0,0,0};
#pragma unroll 4
    for (int k=0;k<128;k++){
        float a0 = Ys[r0][k], a1 = Ys[r0+1][k];
        float4 w = *(const float4*)&Ws[k][col];
        a0c[0]+=a0*w.x; a0c[1]+=a0*w.y; a0c[2]+=a0*w.z; a0c[3]+=a0*w.w;
        a1c[0]+=a1*w.x; a1c[1]+=a1*w.y; a1c[2]+=a1*w.z; a1c[3]+=a1*w.w;
    }
#pragma unroll
    for (int rr=0;rr<2;rr++){
        int m = m0 + r0 + rr;
        int hh = m & 15;
        float dv = Dp[hh];
        float* accp = rr ? a1c : a0c;
#pragma unroll
        for (int j2=0;j2<4;j2++){
            int o = m*64 + col + j2;
            float v = accp[j2] + dv * g_xsilu[o];
            g_y3[o] = v * g_zsilu[o];
        }
    }
}

// ---------------- launch ----------------
extern "C" void kernel_launch(void* const* d_in, const int* in_sizes, int n_in,
                              void* d_out, int out_size)
{
    const float* u        = (const float*)d_in[0];
    const float* W_in     = (const float*)d_in[1];
    const float* b_in     = (const float*)d_in[2];
    const float* W_xup    = (const float*)d_in[3];
    const float* W_ydown  = (const float*)d_in[4];
    const float* A_log    = (const float*)d_in[5];
    const float* theta_log= (const float*)d_in[6];
    const float* D_param  = (const float*)d_in[7];
    const float* wB       = (const float*)d_in[8];
    const float* wC       = (const float*)d_in[9];
    const float* bias_B   = (const float*)d_in[10];
    const float* bias_C   = (const float*)d_in[11];
    const float* W_out    = (const float*)d_in[12];
    float* out = (float*)d_out;

    float *p_proj, *p_y3;
    cudaGetSymbolAddress((void**)&p_proj, g_proj);
    cudaGetSymbolAddress((void**)&p_y3,   g_y3);

    // 1. proj = u @ W_in + b_in   [2048 x 2568, K=512]   bf16-split HMMA, 2 CTA/SM
    {
        dim3 grid((DPROJ + 127)/128, LSEQ/128);
        k_gemm_bf16s<128><<<grid, 256>>>(LSEQ, DPROJ, DMODEL, u, W_in, b_in, p_proj);
    }
    // 2. gates / rmsnorm / dt
    k_post<<<LSEQ, 256>>>(wB, wC, bias_B, bias_C, A_log);
    // 3. dt cumsum + chunk decays
    k_scan_dt<<<1, 128>>>(A_log);
    // 4. RoPE
    k_rope<<<(LSEQ*GN*16 + 255)/256, 256>>>(theta_log);
    // 5. x_up
    k_xup<<<(LSEQ*HH)/16, 256>>>(W_xup);
    // 6-8. chunked recurrence
    k_passA<<<dim3(16, HH, NC), 128>>>();
    k_passB<<<128, 256>>>();
    k_passC<<<dim3(16, HH, NC), 128>>>();
    // 9. ydown + skip + gate
    k_ydown<<<(LSEQ*HH)/16, 128>>>(W_ydown, D_param);
    // 10. out = y3 @ W_out   [2048 x 512, K=1024]   bf16-split HMMA, one full wave
    {
        dim3 grid(DMODEL/64, LSEQ/128);
        k_gemm_bf16s<64><<<grid, 256>>>(LSEQ, DMODEL, 1024, p_y3, W_out, nullptr, out);
    }
}